// round 11
// baseline (speedup 1.0000x reference)
#include <cuda_runtime.h>
#include <cuda_bf16.h>
#include <cfloat>
#include <cstdint>

#define BATCH 8
#define TPTS 30000
#define NPTS (BATCH*TPTS)
#define H 128
#define R2 4096
#define PTILE 64
#define NTILES (NPTS/PTILE)       // 3750
#define CNTN (3*BATCH*R2)
#define OUTN (3*BATCH*H*R2)       // 12582912
#define PLANEN ((size_t)CNTN*H)

// transposed bf16 weight segments (element offsets): [out][k] K-major
#define W0OFF 0
#define SCOFF 163840
#define W1OFF 327680
#define WCOFF 409600
#define WTOT  425984

#define AS 264              // A row stride in bf16 (K=256 + 8 pad)
#define BS 40               // B row stride in bf16 (K=32 chunk + 8 pad)

// smem byte layout (PTILE=64 rows)
#define SM_SBIN 0
#define SM_AH 1024
#define SM_AL (SM_AH + 64*AS*2)
#define SM_B  (SM_AL + 64*AS*2)           // 68608
#define BBUF  20480                        // Bh 10240 + Bl 10240
#define SMEM_SZ (SM_B + 2*BBUF)            // 109568  -> 2 CTAs/SM

typedef unsigned short u16;

__device__ __align__(16) float g_net[(size_t)NPTS*H];
__device__ __align__(16) float g_plane[2][PLANEN];
__device__ __align__(16) __nv_bfloat16 g_whi[WTOT];
__device__ __align__(16) __nv_bfloat16 g_wlo[WTOT];
__device__ int g_cnt[CNTN];

// ---------------- low-level helpers ----------------
__device__ __forceinline__ uint32_t smem_u32(const void* p) {
    uint32_t a;
    asm("{ .reg .u64 t; cvta.to.shared.u64 t, %1; cvt.u32.u64 %0, t; }" : "=r"(a) : "l"(p));
    return a;
}
__device__ __forceinline__ void cp16(uint32_t dst, const void* src) {
    asm volatile("cp.async.cg.shared.global [%0], [%1], 16;" :: "r"(dst), "l"(src));
}
#define CP_COMMIT() asm volatile("cp.async.commit_group;" ::: "memory")
#define CP_WAIT1()  asm volatile("cp.async.wait_group 1;" ::: "memory")
#define CP_WAIT0()  asm volatile("cp.async.wait_group 0;" ::: "memory")

__device__ __forceinline__ void ldmx4(uint32_t r[4], uint32_t addr) {
    asm volatile("ldmatrix.sync.aligned.m8n8.x4.shared.b16 {%0,%1,%2,%3}, [%4];"
        : "=r"(r[0]), "=r"(r[1]), "=r"(r[2]), "=r"(r[3]) : "r"(addr));
}
__device__ __forceinline__ void mma16816(float c[4], const uint32_t a[4], uint32_t b0, uint32_t b1) {
    asm volatile("mma.sync.aligned.m16n8k16.row.col.f32.bf16.bf16.f32 "
        "{%0,%1,%2,%3}, {%4,%5,%6,%7}, {%8,%9}, {%0,%1,%2,%3};"
        : "+f"(c[0]), "+f"(c[1]), "+f"(c[2]), "+f"(c[3])
        : "r"(a[0]), "r"(a[1]), "r"(a[2]), "r"(a[3]), "r"(b0), "r"(b1));
}

// bf16 split: v = hi + lo
__device__ __forceinline__ void dec2(float v, u16& h, u16& l) {
    __nv_bfloat16 hb = __float2bfloat16(v);
    float hf = __bfloat162float(hb);
    __nv_bfloat16 lb = __float2bfloat16(v - hf);
    h = *(u16*)&hb; l = *(u16*)&lb;
}
__device__ __forceinline__ uint32_t dec2pack(float v0, float v1, uint32_t& lop) {
    u16 h0, l0, h1, l1;
    dec2(v0, h0, l0); dec2(v1, h1, l1);
    lop = (uint32_t)l0 | ((uint32_t)l1 << 16);
    return (uint32_t)h0 | ((uint32_t)h1 << 16);
}

// exact relu on split fragments: sign(x) == sign(hi)
__device__ __forceinline__ void frag_relu(uint32_t ah[4], uint32_t al[4]) {
    __nv_bfloat162 z = __float2bfloat162_rn(0.f);
#pragma unroll
    for (int i = 0; i < 4; i++) {
        __nv_bfloat162 h = *(__nv_bfloat162*)&ah[i];
        __nv_bfloat162 l = *(__nv_bfloat162*)&al[i];
        __nv_bfloat162 m = __hgt2(h, z);
        h = __hmax2(h, z);
        l = __hmul2(l, m);
        ah[i] = *(uint32_t*)&h; al[i] = *(uint32_t*)&l;
    }
}

// order-independent float atomic max (bit-deterministic)
__device__ __forceinline__ void amaxf(float* a, float v) {
    if (v >= 0.0f) atomicMax((int*)a, __float_as_int(v));
    else           atomicMin((unsigned int*)a, __float_as_uint(v));
}

// ---------------- B chunk loader (K=32 chunk, hi+lo, 256 threads) ----------------
__device__ __forceinline__ void load_b(uint32_t smb, const __nv_bfloat16* __restrict__ wh,
                                       const __nv_bfloat16* __restrict__ wl,
                                       int K, int c, int buf, int tid) {
    int n = tid >> 1, half = tid & 1;
    uint32_t d = smb + SM_B + buf * BBUF + n * (BS * 2) + half * 32;
    const __nv_bfloat16* sh = wh + (size_t)n * K + c * 32 + half * 16;
    const __nv_bfloat16* sl = wl + (size_t)n * K + c * 32 + half * 16;
    cp16(d, sh);              cp16(d + 16, sh + 8);
    cp16(d + 10240, sl);      cp16(d + 10240 + 16, sl + 8);
    CP_COMMIT();
}

// ---------------- GEMM stage: acc += (relu?)(A) @ W^T, 3-pass split ----------------
// 8 warps: m0 = 32*(wid>>2); n0 = 32*(wid&3). Warp tile 32x32.
template<bool RELU, bool PRE>
__device__ void gemm_stage(uint32_t smb, const __nv_bfloat16* __restrict__ wh,
                           const __nv_bfloat16* __restrict__ wl, int K,
                           float acc[2][4][4], int lane, int m0, int n0, int tid) {
    int nch = K >> 5;
    if (!PRE) load_b(smb, wh, wl, K, 0, 0, tid);
    for (int c = 0; c < nch; c++) {
        if (c + 1 < nch) { load_b(smb, wh, wl, K, c + 1, (c + 1) & 1, tid); CP_WAIT1(); }
        else CP_WAIT0();
        __syncthreads();
        uint32_t bbh = smb + SM_B + (c & 1) * BBUF;
        uint32_t bbl = bbh + 10240;
#pragma unroll
        for (int ks = 0; ks < 2; ks++) {
            int kr = c * 32 + ks * 16;
            uint32_t a_h[2][4], a_l[2][4];
#pragma unroll
            for (int mt = 0; mt < 2; mt++) {
                uint32_t off = (uint32_t)((m0 + mt * 16 + (lane & 15)) * AS + kr + ((lane >> 4) << 3)) * 2;
                ldmx4(a_h[mt], smb + SM_AH + off);
                ldmx4(a_l[mt], smb + SM_AL + off);
                if (RELU) frag_relu(a_h[mt], a_l[mt]);
            }
            uint32_t bh0[4], bh1[4], bl0[4], bl1[4];
#pragma unroll
            for (int np = 0; np < 2; np++) {
                uint32_t boff = (uint32_t)((n0 + np * 16 + (lane & 15)) * BS + ks * 16 + ((lane >> 4) << 3)) * 2;
                uint32_t r[4];
                ldmx4(r, bbh + boff);
                bh0[2*np] = r[0]; bh0[2*np+1] = r[1]; bh1[2*np] = r[2]; bh1[2*np+1] = r[3];
                ldmx4(r, bbl + boff);
                bl0[2*np] = r[0]; bl0[2*np+1] = r[1]; bl1[2*np] = r[2]; bl1[2*np+1] = r[3];
            }
#pragma unroll
            for (int mt = 0; mt < 2; mt++)
#pragma unroll
                for (int nt = 0; nt < 4; nt++) mma16816(acc[mt][nt], a_h[mt], bh0[nt], bh1[nt]);
#pragma unroll
            for (int mt = 0; mt < 2; mt++)
#pragma unroll
                for (int nt = 0; nt < 4; nt++) mma16816(acc[mt][nt], a_l[mt], bh0[nt], bh1[nt]);
#pragma unroll
            for (int mt = 0; mt < 2; mt++)
#pragma unroll
                for (int nt = 0; nt < 4; nt++) mma16816(acc[mt][nt], a_h[mt], bl0[nt], bl1[nt]);
        }
        __syncthreads();
    }
}

__device__ __forceinline__ void zero_acc(float acc[2][4][4]) {
#pragma unroll
    for (int i = 0; i < 2; i++)
#pragma unroll
        for (int j = 0; j < 4; j++)
#pragma unroll
            for (int k = 0; k < 4; k++) acc[i][j][k] = 0.f;
}

// ---------------- fused resnet block (+ scatter-max pooling in epilogue) ----------------
__global__ void __launch_bounds__(256, 2)
resnet_kernel(int mode,
              const float* __restrict__ pts,
              const int* __restrict__ ixz, const int* __restrict__ ixy,
              const int* __restrict__ iyz,
              const float* __restrict__ fcpw, const float* __restrict__ fcpb,
              int blk,
              const float* __restrict__ fc0b, const float* __restrict__ fc1b,
              int rdbuf, int wrbuf, int do_scatter) {
    extern __shared__ char smem[];
    uint32_t smb = smem_u32(smem);
    int tid = threadIdx.x;
    int lane = tid & 31, wid = tid >> 5;
    int m0 = (wid >> 2) * 32, n0 = (wid & 3) * 32;
    int pbase = blockIdx.x * PTILE;
    int* sbin = (int*)(smem + SM_SBIN);

    const __nv_bfloat16* w0hi = g_whi + W0OFF + (size_t)blk * 32768;
    const __nv_bfloat16* w0lo = g_wlo + W0OFF + (size_t)blk * 32768;
    const __nv_bfloat16* schi = g_whi + SCOFF + (size_t)blk * 32768;
    const __nv_bfloat16* sclo = g_wlo + SCOFF + (size_t)blk * 32768;
    const __nv_bfloat16* w1hi = g_whi + W1OFF + (size_t)blk * 16384;
    const __nv_bfloat16* w1lo = g_wlo + W1OFF + (size_t)blk * 16384;

    // hoist first B chunk (shortcut) so DMA overlaps the A fill
    load_b(smb, schi, sclo, 256, 0, 0, tid);

    // sbin (always: fill-gather in mode 1, scatter in all scatter rounds)
    if (tid < 192) {
        int pl = tid >> 6, s = tid & 63;
        int gp = pbase + s;
        int b = gp / TPTS;
        const int* ix = (pl == 0) ? ixz : (pl == 1) ? ixy : iyz;
        sbin[pl * 64 + s] = (pl * BATCH + b) * R2 + ix[gp];
    }
    __syncthreads();

    const float* plr = g_plane[rdbuf];
    float* plw = g_plane[wrbuf];

    // ---- fill A (x) hi/lo: thread handles column k for all 64 points ----
    {
        int k = tid;
        u16* ah = (u16*)(smem + SM_AH) + k;
        u16* al = (u16*)(smem + SM_AL) + k;
        if (mode == 0) {
            float wk0 = fcpw[k], wk1 = fcpw[256 + k], wk2 = fcpw[512 + k];
            float bk = fcpb[k];
            for (int s = 0; s < PTILE; s++) {
                int gp = pbase + s;
                float v = bk + pts[gp*3]*wk0 + pts[gp*3+1]*wk1 + pts[gp*3+2]*wk2;
                u16 h, l; dec2(v, h, l);
                ah[s * AS] = h; al[s * AS] = l;
            }
        } else if (k < H) {
            for (int s = 0; s < PTILE; s++) {
                float v = g_net[(size_t)(pbase + s) * H + k];
                u16 h, l; dec2(v, h, l);
                ah[s * AS] = h; al[s * AS] = l;
            }
        } else {
            int ch = k - H;
            for (int s = 0; s < PTILE; s++) {
                float v = plr[(size_t)sbin[s] * H + ch]
                        + plr[(size_t)sbin[64 + s] * H + ch]
                        + plr[(size_t)sbin[128 + s] * H + ch];
                u16 h, l; dec2(v, h, l);
                ah[s * AS] = h; al[s * AS] = l;
            }
        }
    }
    // (sync inside gemm_stage orders fill vs ldmatrix)

    float acc_sc[2][4][4], acc[2][4][4];

    // ---- shortcut: acc_sc = x @ wsc^T (kept in registers) ----
    zero_acc(acc_sc);
    gemm_stage<false, true>(smb, schi, sclo, 256, acc_sc, lane, m0, n0, tid);

    // ---- fc0: acc = relu(x) @ w0^T ----
    zero_acc(acc);
    gemm_stage<true, false>(smb, w0hi, w0lo, 256, acc, lane, m0, n0, tid);

    // epilogue1: ns = relu(acc + b0) -> overwrite A region (cols 0..127)
#pragma unroll
    for (int mt = 0; mt < 2; mt++)
#pragma unroll
        for (int nt = 0; nt < 4; nt++) {
            int row = m0 + mt * 16 + (lane >> 2);
            int col = n0 + nt * 8 + (lane & 3) * 2;
            float ba = fc0b[col], bb = fc0b[col + 1];
            uint32_t lo, hi;
            hi = dec2pack(fmaxf(acc[mt][nt][0] + ba, 0.f), fmaxf(acc[mt][nt][1] + bb, 0.f), lo);
            *(uint32_t*)(smem + SM_AH + (row * AS + col) * 2) = hi;
            *(uint32_t*)(smem + SM_AL + (row * AS + col) * 2) = lo;
            hi = dec2pack(fmaxf(acc[mt][nt][2] + ba, 0.f), fmaxf(acc[mt][nt][3] + bb, 0.f), lo);
            *(uint32_t*)(smem + SM_AH + ((row + 8) * AS + col) * 2) = hi;
            *(uint32_t*)(smem + SM_AL + ((row + 8) * AS + col) * 2) = lo;
        }

    // ---- fc1: acc_sc += ns @ w1^T; out = acc_sc + b1; fused scatter-max ----
    gemm_stage<false, false>(smb, w1hi, w1lo, 128, acc_sc, lane, m0, n0, tid);
#pragma unroll
    for (int mt = 0; mt < 2; mt++)
#pragma unroll
        for (int nt = 0; nt < 4; nt++) {
            int s0 = m0 + mt * 16 + (lane >> 2);
            int s1 = s0 + 8;
            int col = n0 + nt * 8 + (lane & 3) * 2;
            float ba = fc1b[col], bb = fc1b[col + 1];
            float v0 = acc_sc[mt][nt][0] + ba, v1 = acc_sc[mt][nt][1] + bb;
            float v2 = acc_sc[mt][nt][2] + ba, v3 = acc_sc[mt][nt][3] + bb;
            *(float2*)&g_net[(size_t)(pbase + s0) * H + col] = make_float2(v0, v1);
            *(float2*)&g_net[(size_t)(pbase + s1) * H + col] = make_float2(v2, v3);
            if (do_scatter) {
#pragma unroll
                for (int pl = 0; pl < 3; pl++) {
                    float* p0 = plw + (size_t)sbin[pl * 64 + s0] * H + col;
                    amaxf(p0, v0); amaxf(p0 + 1, v1);
                    float* p1 = plw + (size_t)sbin[pl * 64 + s1] * H + col;
                    amaxf(p1, v2); amaxf(p1 + 1, v3);
                }
            }
        }
}

// ---------------- final projection + fused scatter-mean (atomicAdd) ----------------
__global__ void __launch_bounds__(256, 2)
proj_kernel(const int* __restrict__ ixz, const int* __restrict__ ixy,
            const int* __restrict__ iyz,
            const float* __restrict__ bc, float* __restrict__ out) {
    extern __shared__ char smem[];
    uint32_t smb = smem_u32(smem);
    int tid = threadIdx.x;
    int lane = tid & 31, wid = tid >> 5;
    int m0 = (wid >> 2) * 32, n0 = (wid & 3) * 32;
    int pbase = blockIdx.x * PTILE;
    int* sbin = (int*)(smem + SM_SBIN);

    load_b(smb, g_whi + WCOFF, g_wlo + WCOFF, 128, 0, 0, tid);

    if (tid < 192) {
        int pl = tid >> 6, s = tid & 63;
        int gp = pbase + s;
        int b = gp / TPTS;
        const int* ix = (pl == 0) ? ixz : (pl == 1) ? ixy : iyz;
        sbin[pl * 64 + s] = (pl * BATCH + b) * R2 + ix[gp];
    }
    __syncthreads();

    {
        int k = tid & 127;
        int s0 = (tid >> 7) * 32;
        u16* ah = (u16*)(smem + SM_AH) + k;
        u16* al = (u16*)(smem + SM_AL) + k;
        for (int s = s0; s < s0 + 32; s++) {
            float v = g_net[(size_t)(pbase + s) * H + k];
            u16 h, l; dec2(v, h, l);
            ah[s * AS] = h; al[s * AS] = l;
        }
    }

    float acc[2][4][4];
    zero_acc(acc);
    gemm_stage<false, true>(smb, g_whi + WCOFF, g_wlo + WCOFF, 128, acc, lane, m0, n0, tid);
#pragma unroll
    for (int mt = 0; mt < 2; mt++)
#pragma unroll
        for (int nt = 0; nt < 4; nt++) {
            int s0 = m0 + mt * 16 + (lane >> 2);
            int s1 = s0 + 8;
            int col = n0 + nt * 8 + (lane & 3) * 2;
            float ba = bc[col], bb = bc[col + 1];
            float v0 = acc[mt][nt][0] + ba, v1 = acc[mt][nt][1] + bb;
            float v2 = acc[mt][nt][2] + ba, v3 = acc[mt][nt][3] + bb;
#pragma unroll
            for (int pl = 0; pl < 3; pl++) {
                int b0 = sbin[pl * 64 + s0];
                size_t o0 = (size_t)(b0 >> 12) * 524288 + (size_t)col * 4096 + (b0 & 4095);
                atomicAdd(out + o0, v0);
                atomicAdd(out + o0 + 4096, v1);
                int b1 = sbin[pl * 64 + s1];
                size_t o1 = (size_t)(b1 >> 12) * 524288 + (size_t)col * 4096 + (b1 & 4095);
                atomicAdd(out + o1, v2);
                atomicAdd(out + o1 + 4096, v3);
            }
        }
}

// ---------------- weight prep: transpose + hi/lo decompose ----------------
__global__ void prep_w_kernel(const float* __restrict__ fc0w, const float* __restrict__ fc1w,
                              const float* __restrict__ scw,  const float* __restrict__ fccw) {
    int idx = blockIdx.x * 256 + threadIdx.x;
    if (idx >= WTOT) return;
    float v;
    if (idx < SCOFF) {
        int blk = idx >> 15, r = idx & 32767, out = r >> 8, k = r & 255;
        v = fc0w[((size_t)blk * 256 + k) * 128 + out];
    } else if (idx < W1OFF) {
        int i = idx - SCOFF;
        int blk = i >> 15, r = i & 32767, out = r >> 8, k = r & 255;
        v = scw[((size_t)blk * 256 + k) * 128 + out];
    } else if (idx < WCOFF) {
        int i = idx - W1OFF;
        int blk = i >> 14, r = i & 16383, out = r >> 7, k = r & 127;
        v = fc1w[((size_t)blk * 128 + k) * 128 + out];
    } else {
        int i = idx - WCOFF;
        int out = i >> 7, k = i & 127;
        v = fccw[(size_t)k * 128 + out];
    }
    u16 h, l; dec2(v, h, l);
    g_whi[idx] = *(__nv_bfloat16*)&h;
    g_wlo[idx] = *(__nv_bfloat16*)&l;
}

// ============ aux kernels ============
__global__ void init_plane_kernel(int buf) {
    size_t i = (size_t)blockIdx.x * 256 + threadIdx.x;    // over PLANEN/4
    uint4 v = make_uint4(0xFF7FFFFFu, 0xFF7FFFFFu, 0xFF7FFFFFu, 0xFF7FFFFFu);
    ((uint4*)g_plane[buf])[i] = v;
}

__global__ void zero_out_kernel(float* __restrict__ out) {
    size_t i = (size_t)blockIdx.x * 256 + threadIdx.x;    // over OUTN/4
    ((float4*)out)[i] = make_float4(0.f, 0.f, 0.f, 0.f);
    if (i < CNTN) g_cnt[i] = 0;
}

__global__ void count_kernel(const int* __restrict__ ixz, const int* __restrict__ ixy,
                             const int* __restrict__ iyz) {
    int p = blockIdx.x * 256 + threadIdx.x;
    if (p >= NPTS) return;
    int b = p / TPTS;
    atomicAdd(&g_cnt[(0 * BATCH + b) * R2 + ixz[p]], 1);
    atomicAdd(&g_cnt[(1 * BATCH + b) * R2 + ixy[p]], 1);
    atomicAdd(&g_cnt[(2 * BATCH + b) * R2 + iyz[p]], 1);
}

__global__ void div_kernel(float* __restrict__ out) {
    size_t i = (size_t)blockIdx.x * 256 + threadIdx.x;    // over OUTN
    int c = g_cnt[(i >> 19) * R2 + (i & 4095)];
    out[i] = out[i] / fmaxf((float)c, 1.0f);
}

extern "C" void kernel_launch(void* const* d_in, const int* in_sizes, int n_in,
                              void* d_out, int out_size) {
    const float* pts  = (const float*)d_in[0];
    const int*   ixz  = (const int*)d_in[1];
    const int*   ixy  = (const int*)d_in[2];
    const int*   iyz  = (const int*)d_in[3];
    const float* fcpw = (const float*)d_in[4];
    const float* fcpb = (const float*)d_in[5];
    const float* fc0w = (const float*)d_in[6];
    const float* fc0b = (const float*)d_in[7];
    const float* fc1w = (const float*)d_in[8];
    const float* fc1b = (const float*)d_in[9];
    const float* scw  = (const float*)d_in[10];
    const float* fccw = (const float*)d_in[11];
    const float* fccb = (const float*)d_in[12];
    float* out = (float*)d_out;

    cudaFuncSetAttribute(resnet_kernel, cudaFuncAttributeMaxDynamicSharedMemorySize, SMEM_SZ);
    cudaFuncSetAttribute(proj_kernel,   cudaFuncAttributeMaxDynamicSharedMemorySize, SMEM_SZ);

    prep_w_kernel<<<(WTOT + 255) / 256, 256>>>(fc0w, fc1w, scw, fccw);       // 0
    zero_out_kernel<<<OUTN / 4 / 256, 256>>>(out);                           // 1
    init_plane_kernel<<<(int)(PLANEN / 4 / 256), 256>>>(0);                  // 2
    // resnet0 at index 3 (ncu -s 5 lands here with the 2 harness pre-launches)
    resnet_kernel<<<NTILES, 256, SMEM_SZ>>>(0, pts, ixz, ixy, iyz, fcpw, fcpb,
                                            0, fc0b, fc1b, 0, 0, 1);         // 3: scatter -> buf0
    count_kernel<<<(NPTS + 255) / 256, 256>>>(ixz, ixy, iyz);                // 4
    init_plane_kernel<<<(int)(PLANEN / 4 / 256), 256>>>(1);                  // 5

    // blocks 1..4: read plane[rd], scatter -> plane[wr] (except last)
    int rd = 0;
    for (int it = 1; it < 5; it++) {
        int wr = rd ^ 1;
        int do_sc = (it < 4) ? 1 : 0;
        resnet_kernel<<<NTILES, 256, SMEM_SZ>>>(1, pts, ixz, ixy, iyz, fcpw, fcpb,
                                                it, fc0b + (size_t)it * H,
                                                fc1b + (size_t)it * H,
                                                rd, wr, do_sc);
        if (it < 3) init_plane_kernel<<<(int)(PLANEN / 4 / 256), 256>>>(rd); // re-init for next scatter
        rd = wr;
    }

    proj_kernel<<<NTILES, 256, SMEM_SZ>>>(ixz, ixy, iyz, fccb, out);
    div_kernel<<<OUTN / 256, 256>>>(out);
}

// round 12
// speedup vs baseline: 1.2326x; 1.2326x over previous
#include <cuda_runtime.h>
#include <cuda_bf16.h>
#include <cfloat>
#include <cstdint>

#define BATCH 8
#define TPTS 30000
#define NPTS (BATCH*TPTS)
#define H 128
#define R2 4096
#define PTILE 128
#define NTILES (NPTS/PTILE)       // 1875
#define CNTN (3*BATCH*R2)

// transposed bf16 weight segments (element offsets): [out][k] K-major
#define W0OFF 0
#define SCOFF 163840
#define W1OFF 327680
#define WCOFF 409600
#define WTOT  425984

#define AS 264              // A row stride in bf16 (K=256 + 8 pad)
#define BSB 72              // B row stride in bf16 (K=64 chunk + 8 pad) -> 144B, ldmatrix conflict-free

// smem byte layout (PTILE=128 rows)
#define SM_SBIN 0
#define SM_AH 2048
#define SM_AL (SM_AH + 128*AS*2)          // 69632
#define SM_B  (SM_AL + 128*AS*2)          // 137216
#define HIB   (128*BSB*2)                  // 18432 (one hi or lo chunk)
#define BBUF  (2*HIB)                      // 36864 (hi+lo)
#define SMEM_SZ (SM_B + 2*BBUF)            // 210944 -> 1 CTA/SM

typedef unsigned short u16;

__device__ __align__(16) float g_net[(size_t)NPTS*H];
__device__ __align__(16) float g_c[(size_t)NPTS*H];
__device__ __align__(16) float g_plane[(size_t)CNTN*H];
__device__ __align__(16) __nv_bfloat16 g_whi[WTOT];
__device__ __align__(16) __nv_bfloat16 g_wlo[WTOT];
__device__ int g_cnt[CNTN], g_start[CNTN], g_cursor[CNTN];
__device__ int g_sorted[3*NPTS];
__device__ int g_bsum[96];

// ---------------- low-level helpers ----------------
__device__ __forceinline__ uint32_t smem_u32(const void* p) {
    uint32_t a;
    asm("{ .reg .u64 t; cvta.to.shared.u64 t, %1; cvt.u32.u64 %0, t; }" : "=r"(a) : "l"(p));
    return a;
}
__device__ __forceinline__ void cp16(uint32_t dst, const void* src) {
    asm volatile("cp.async.cg.shared.global [%0], [%1], 16;" :: "r"(dst), "l"(src));
}
#define CP_COMMIT() asm volatile("cp.async.commit_group;" ::: "memory")
#define CP_WAIT1()  asm volatile("cp.async.wait_group 1;" ::: "memory")
#define CP_WAIT0()  asm volatile("cp.async.wait_group 0;" ::: "memory")

__device__ __forceinline__ void ldmx4(uint32_t r[4], uint32_t addr) {
    asm volatile("ldmatrix.sync.aligned.m8n8.x4.shared.b16 {%0,%1,%2,%3}, [%4];"
        : "=r"(r[0]), "=r"(r[1]), "=r"(r[2]), "=r"(r[3]) : "r"(addr));
}
__device__ __forceinline__ void mma16816(float c[4], const uint32_t a[4], uint32_t b0, uint32_t b1) {
    asm volatile("mma.sync.aligned.m16n8k16.row.col.f32.bf16.bf16.f32 "
        "{%0,%1,%2,%3}, {%4,%5,%6,%7}, {%8,%9}, {%0,%1,%2,%3};"
        : "+f"(c[0]), "+f"(c[1]), "+f"(c[2]), "+f"(c[3])
        : "r"(a[0]), "r"(a[1]), "r"(a[2]), "r"(a[3]), "r"(b0), "r"(b1));
}

// bf16 split: v = hi + lo
__device__ __forceinline__ void dec2(float v, u16& h, u16& l) {
    __nv_bfloat16 hb = __float2bfloat16(v);
    float hf = __bfloat162float(hb);
    __nv_bfloat16 lb = __float2bfloat16(v - hf);
    h = *(u16*)&hb; l = *(u16*)&lb;
}
__device__ __forceinline__ uint32_t dec2pack(float v0, float v1, uint32_t& lop) {
    u16 h0, l0, h1, l1;
    dec2(v0, h0, l0); dec2(v1, h1, l1);
    lop = (uint32_t)l0 | ((uint32_t)l1 << 16);
    return (uint32_t)h0 | ((uint32_t)h1 << 16);
}

// exact relu on split fragments: sign(x) == sign(hi)
__device__ __forceinline__ void frag_relu(uint32_t ah[4], uint32_t al[4]) {
    __nv_bfloat162 z = __float2bfloat162_rn(0.f);
#pragma unroll
    for (int i = 0; i < 4; i++) {
        __nv_bfloat162 h = *(__nv_bfloat162*)&ah[i];
        __nv_bfloat162 l = *(__nv_bfloat162*)&al[i];
        __nv_bfloat162 m = __hgt2(h, z);
        h = __hmax2(h, z);
        l = __hmul2(l, m);
        ah[i] = *(uint32_t*)&h; al[i] = *(uint32_t*)&l;
    }
}

// ---------------- B chunk loader (K=64 chunk, hi+lo, 512 threads) ----------------
__device__ __forceinline__ void load_b(uint32_t smb, const __nv_bfloat16* __restrict__ wh,
                                       const __nv_bfloat16* __restrict__ wl,
                                       int K, int c, int buf, int tid) {
    int n = tid >> 2, qq = tid & 3;
    uint32_t d = smb + SM_B + buf * BBUF + n * (BSB * 2) + qq * 32;
    const __nv_bfloat16* sh = wh + (size_t)n * K + c * 64 + qq * 16;
    const __nv_bfloat16* sl = wl + (size_t)n * K + c * 64 + qq * 16;
    cp16(d, sh);            cp16(d + 16, sh + 8);
    cp16(d + HIB, sl);      cp16(d + HIB + 16, sl + 8);
    CP_COMMIT();
}

// ---------------- GEMM stage: acc += (relu?)(A) @ W^T, 3-pass split ----------------
// 16 warps: m0 = 32*(wid>>2); n0 = 32*(wid&3). Warp tile 32x32.
template<bool RELU, bool PRE>
__device__ void gemm_stage(uint32_t smb, const __nv_bfloat16* __restrict__ wh,
                           const __nv_bfloat16* __restrict__ wl, int K,
                           float acc[2][4][4], int lane, int m0, int n0, int tid) {
    int nch = K >> 6;
    if (!PRE) load_b(smb, wh, wl, K, 0, 0, tid);
    for (int c = 0; c < nch; c++) {
        if (c + 1 < nch) { load_b(smb, wh, wl, K, c + 1, (c + 1) & 1, tid); CP_WAIT1(); }
        else CP_WAIT0();
        __syncthreads();
        uint32_t bbh = smb + SM_B + (c & 1) * BBUF;
        uint32_t bbl = bbh + HIB;
#pragma unroll
        for (int ks = 0; ks < 4; ks++) {
            int kr = c * 64 + ks * 16;
            uint32_t a_h[2][4], a_l[2][4];
#pragma unroll
            for (int mt = 0; mt < 2; mt++) {
                uint32_t off = (uint32_t)((m0 + mt * 16 + (lane & 15)) * AS + kr + ((lane >> 4) << 3)) * 2;
                ldmx4(a_h[mt], smb + SM_AH + off);
                ldmx4(a_l[mt], smb + SM_AL + off);
                if (RELU) frag_relu(a_h[mt], a_l[mt]);
            }
            uint32_t bh0[4], bh1[4], bl0[4], bl1[4];
#pragma unroll
            for (int np = 0; np < 2; np++) {
                uint32_t boff = (uint32_t)((n0 + np * 16 + (lane & 15)) * BSB + ks * 16 + ((lane >> 4) << 3)) * 2;
                uint32_t r[4];
                ldmx4(r, bbh + boff);
                bh0[2*np] = r[0]; bh0[2*np+1] = r[1]; bh1[2*np] = r[2]; bh1[2*np+1] = r[3];
                ldmx4(r, bbl + boff);
                bl0[2*np] = r[0]; bl0[2*np+1] = r[1]; bl1[2*np] = r[2]; bl1[2*np+1] = r[3];
            }
#pragma unroll
            for (int mt = 0; mt < 2; mt++)
#pragma unroll
                for (int nt = 0; nt < 4; nt++) mma16816(acc[mt][nt], a_h[mt], bh0[nt], bh1[nt]);
#pragma unroll
            for (int mt = 0; mt < 2; mt++)
#pragma unroll
                for (int nt = 0; nt < 4; nt++) mma16816(acc[mt][nt], a_l[mt], bh0[nt], bh1[nt]);
#pragma unroll
            for (int mt = 0; mt < 2; mt++)
#pragma unroll
                for (int nt = 0; nt < 4; nt++) mma16816(acc[mt][nt], a_h[mt], bl0[nt], bl1[nt]);
        }
        __syncthreads();
    }
}

__device__ __forceinline__ void zero_acc(float acc[2][4][4]) {
#pragma unroll
    for (int i = 0; i < 2; i++)
#pragma unroll
        for (int j = 0; j < 4; j++)
#pragma unroll
            for (int k = 0; k < 4; k++) acc[i][j][k] = 0.f;
}

// ---------------- fused resnet block ----------------
__global__ void __launch_bounds__(512, 1)
resnet_kernel(int mode,
              const float* __restrict__ pts,
              const int* __restrict__ ixz, const int* __restrict__ ixy,
              const int* __restrict__ iyz,
              const float* __restrict__ fcpw, const float* __restrict__ fcpb,
              int blk,
              const float* __restrict__ fc0b, const float* __restrict__ fc1b) {
    extern __shared__ char smem[];
    uint32_t smb = smem_u32(smem);
    int tid = threadIdx.x;
    int lane = tid & 31, wid = tid >> 5;
    int m0 = (wid >> 2) * 32, n0 = (wid & 3) * 32;
    int pbase = blockIdx.x * PTILE;
    int* sbin = (int*)(smem + SM_SBIN);

    const __nv_bfloat16* w0hi = g_whi + W0OFF + (size_t)blk * 32768;
    const __nv_bfloat16* w0lo = g_wlo + W0OFF + (size_t)blk * 32768;
    const __nv_bfloat16* schi = g_whi + SCOFF + (size_t)blk * 32768;
    const __nv_bfloat16* sclo = g_wlo + SCOFF + (size_t)blk * 32768;
    const __nv_bfloat16* w1hi = g_whi + W1OFF + (size_t)blk * 16384;
    const __nv_bfloat16* w1lo = g_wlo + W1OFF + (size_t)blk * 16384;

    // hoist first B chunk (shortcut) so DMA overlaps the A fill
    load_b(smb, schi, sclo, 256, 0, 0, tid);

    if (mode == 1 && tid < PTILE) {
        int gp = pbase + tid;
        int b = gp / TPTS;
        sbin[tid]             = (0 * BATCH + b) * R2 + ixz[gp];
        sbin[PTILE + tid]     = (1 * BATCH + b) * R2 + ixy[gp];
        sbin[2 * PTILE + tid] = (2 * BATCH + b) * R2 + iyz[gp];
    }
    __syncthreads();

    // ---- fill A (x) hi/lo: thread handles column k for 64 points ----
    {
        int k = tid & 255;
        int s0 = (tid >> 8) * 64;
        u16* ah = (u16*)(smem + SM_AH) + k;
        u16* al = (u16*)(smem + SM_AL) + k;
        if (mode == 0) {
            float wk0 = fcpw[k], wk1 = fcpw[256 + k], wk2 = fcpw[512 + k];
            float bk = fcpb[k];
            for (int s = s0; s < s0 + 64; s++) {
                int gp = pbase + s;
                float v = bk + pts[gp*3]*wk0 + pts[gp*3+1]*wk1 + pts[gp*3+2]*wk2;
                u16 h, l; dec2(v, h, l);
                ah[s * AS] = h; al[s * AS] = l;
            }
        } else if (k < H) {
            for (int s = s0; s < s0 + 64; s++) {
                float v = g_net[(size_t)(pbase + s) * H + k];
                u16 h, l; dec2(v, h, l);
                ah[s * AS] = h; al[s * AS] = l;
            }
        } else {
            int ch = k - H;
            for (int s = s0; s < s0 + 64; s++) {
                float v = g_plane[(size_t)sbin[s] * H + ch]
                        + g_plane[(size_t)sbin[PTILE + s] * H + ch]
                        + g_plane[(size_t)sbin[2 * PTILE + s] * H + ch];
                u16 h, l; dec2(v, h, l);
                ah[s * AS] = h; al[s * AS] = l;
            }
        }
    }
    // (sync inside gemm_stage orders fill vs ldmatrix)

    float acc_sc[2][4][4], acc[2][4][4];

    // ---- shortcut: acc_sc = x @ wsc^T (kept in registers) ----
    zero_acc(acc_sc);
    gemm_stage<false, true>(smb, schi, sclo, 256, acc_sc, lane, m0, n0, tid);

    // ---- fc0: acc = relu(x) @ w0^T ----
    zero_acc(acc);
    gemm_stage<true, false>(smb, w0hi, w0lo, 256, acc, lane, m0, n0, tid);

    // epilogue1: ns = relu(acc + b0) -> overwrite A region (cols 0..127)
#pragma unroll
    for (int mt = 0; mt < 2; mt++)
#pragma unroll
        for (int nt = 0; nt < 4; nt++) {
            int row = m0 + mt * 16 + (lane >> 2);
            int col = n0 + nt * 8 + (lane & 3) * 2;
            float ba = fc0b[col], bb = fc0b[col + 1];
            uint32_t lo, hi;
            hi = dec2pack(fmaxf(acc[mt][nt][0] + ba, 0.f), fmaxf(acc[mt][nt][1] + bb, 0.f), lo);
            *(uint32_t*)(smem + SM_AH + (row * AS + col) * 2) = hi;
            *(uint32_t*)(smem + SM_AL + (row * AS + col) * 2) = lo;
            hi = dec2pack(fmaxf(acc[mt][nt][2] + ba, 0.f), fmaxf(acc[mt][nt][3] + bb, 0.f), lo);
            *(uint32_t*)(smem + SM_AH + ((row + 8) * AS + col) * 2) = hi;
            *(uint32_t*)(smem + SM_AL + ((row + 8) * AS + col) * 2) = lo;
        }

    // ---- fc1: acc_sc += ns @ w1^T; out = acc_sc + b1 ----
    gemm_stage<false, false>(smb, w1hi, w1lo, 128, acc_sc, lane, m0, n0, tid);
#pragma unroll
    for (int mt = 0; mt < 2; mt++)
#pragma unroll
        for (int nt = 0; nt < 4; nt++) {
            int row = pbase + m0 + mt * 16 + (lane >> 2);
            int col = n0 + nt * 8 + (lane & 3) * 2;
            float ba = fc1b[col], bb = fc1b[col + 1];
            *(float2*)&g_net[(size_t)row * H + col] =
                make_float2(acc_sc[mt][nt][0] + ba, acc_sc[mt][nt][1] + bb);
            *(float2*)&g_net[(size_t)(row + 8) * H + col] =
                make_float2(acc_sc[mt][nt][2] + ba, acc_sc[mt][nt][3] + bb);
        }
}

// ---------------- final projection: g_c = net @ wc^T + bc ----------------
__global__ void __launch_bounds__(512, 1)
proj_kernel(const float* __restrict__ bc) {
    extern __shared__ char smem[];
    uint32_t smb = smem_u32(smem);
    int tid = threadIdx.x;
    int lane = tid & 31, wid = tid >> 5;
    int m0 = (wid >> 2) * 32, n0 = (wid & 3) * 32;
    int pbase = blockIdx.x * PTILE;

    load_b(smb, g_whi + WCOFF, g_wlo + WCOFF, 128, 0, 0, tid);
    {
        int k = tid & 127;
        int s0 = (tid >> 7) * 32;
        u16* ah = (u16*)(smem + SM_AH) + k;
        u16* al = (u16*)(smem + SM_AL) + k;
        for (int s = s0; s < s0 + 32; s++) {
            float v = g_net[(size_t)(pbase + s) * H + k];
            u16 h, l; dec2(v, h, l);
            ah[s * AS] = h; al[s * AS] = l;
        }
    }

    float acc[2][4][4];
    zero_acc(acc);
    gemm_stage<false, true>(smb, g_whi + WCOFF, g_wlo + WCOFF, 128, acc, lane, m0, n0, tid);
#pragma unroll
    for (int mt = 0; mt < 2; mt++)
#pragma unroll
        for (int nt = 0; nt < 4; nt++) {
            int row = pbase + m0 + mt * 16 + (lane >> 2);
            int col = n0 + nt * 8 + (lane & 3) * 2;
            float ba = bc[col], bb = bc[col + 1];
            *(float2*)&g_c[(size_t)row * H + col] =
                make_float2(acc[mt][nt][0] + ba, acc[mt][nt][1] + bb);
            *(float2*)&g_c[(size_t)(row + 8) * H + col] =
                make_float2(acc[mt][nt][2] + ba, acc[mt][nt][3] + bb);
        }
}

// ---------------- weight prep: transpose + hi/lo decompose ----------------
__global__ void prep_w_kernel(const float* __restrict__ fc0w, const float* __restrict__ fc1w,
                              const float* __restrict__ scw,  const float* __restrict__ fccw) {
    int idx = blockIdx.x * 256 + threadIdx.x;
    if (idx >= WTOT) return;
    float v;
    if (idx < SCOFF) {
        int blk = idx >> 15, r = idx & 32767, out = r >> 8, k = r & 255;
        v = fc0w[((size_t)blk * 256 + k) * 128 + out];
    } else if (idx < W1OFF) {
        int i = idx - SCOFF;
        int blk = i >> 15, r = i & 32767, out = r >> 8, k = r & 255;
        v = scw[((size_t)blk * 256 + k) * 128 + out];
    } else if (idx < WCOFF) {
        int i = idx - W1OFF;
        int blk = i >> 14, r = i & 16383, out = r >> 7, k = r & 127;
        v = fc1w[((size_t)blk * 128 + k) * 128 + out];
    } else {
        int i = idx - WCOFF;
        int out = i >> 7, k = i & 127;
        v = fccw[(size_t)k * 128 + out];
    }
    u16 h, l; dec2(v, h, l);
    g_whi[idx] = *(__nv_bfloat16*)&h;
    g_wlo[idx] = *(__nv_bfloat16*)&l;
}

// ============ sorted-bin infrastructure ============
__global__ void zero_meta_kernel() {
    int i = blockIdx.x * 256 + threadIdx.x;
    if (i < CNTN) { g_cnt[i] = 0; g_cursor[i] = 0; }
}

__global__ void count_kernel(const int* __restrict__ ixz, const int* __restrict__ ixy,
                             const int* __restrict__ iyz) {
    int p = blockIdx.x * 256 + threadIdx.x;
    if (p >= NPTS) return;
    int b = p / TPTS;
    atomicAdd(&g_cnt[(0 * BATCH + b) * R2 + ixz[p]], 1);
    atomicAdd(&g_cnt[(1 * BATCH + b) * R2 + ixy[p]], 1);
    atomicAdd(&g_cnt[(2 * BATCH + b) * R2 + iyz[p]], 1);
}

__global__ void scan1_kernel() {
    __shared__ int smv[1024];
    int tid = threadIdx.x;
    int i = blockIdx.x * 1024 + tid;
    int v = g_cnt[i];
    smv[tid] = v;
    __syncthreads();
    for (int off = 1; off < 1024; off <<= 1) {
        int t = 0;
        if (tid >= off) t = smv[tid - off];
        __syncthreads();
        if (tid >= off) smv[tid] += t;
        __syncthreads();
    }
    g_start[i] = smv[tid] - v;
    if (tid == 1023) g_bsum[blockIdx.x] = smv[tid];
}

__global__ void scan2_kernel() {
    __shared__ int smv[128];
    int tid = threadIdx.x;
    int v = (tid < 96) ? g_bsum[tid] : 0;
    smv[tid] = v;
    __syncthreads();
    for (int off = 1; off < 128; off <<= 1) {
        int t = 0;
        if (tid >= off) t = smv[tid - off];
        __syncthreads();
        if (tid >= off) smv[tid] += t;
        __syncthreads();
    }
    if (tid < 96) g_bsum[tid] = smv[tid] - v;
}

__global__ void scan3_kernel() {
    int i = blockIdx.x * 256 + threadIdx.x;
    if (i < CNTN) g_start[i] += g_bsum[i >> 10];
}

__global__ void sortfill_kernel(const int* __restrict__ ixz, const int* __restrict__ ixy,
                                const int* __restrict__ iyz) {
    int p = blockIdx.x * 256 + threadIdx.x;
    if (p >= NPTS) return;
    int b = p / TPTS;
    int bins[3];
    bins[0] = (0 * BATCH + b) * R2 + ixz[p];
    bins[1] = (1 * BATCH + b) * R2 + ixy[p];
    bins[2] = (2 * BATCH + b) * R2 + iyz[p];
#pragma unroll
    for (int pl = 0; pl < 3; pl++) {
        int pos = atomicAdd(&g_cursor[bins[pl]], 1);
        g_sorted[g_start[bins[pl]] + pos] = p;
    }
}

__device__ __forceinline__ float4 max4(float4 a, float4 b) {
    return make_float4(fmaxf(a.x, b.x), fmaxf(a.y, b.y), fmaxf(a.z, b.z), fmaxf(a.w, b.w));
}

// pool max: warp-per-bin, float4 channels (lane = 4 channels). grid = CNTN/8, block 256.
__global__ void __launch_bounds__(256)
pool_max_kernel() {
    int w = threadIdx.x >> 5, lane = threadIdx.x & 31;
    int bin = blockIdx.x * 8 + w;
    int n = g_cnt[bin];
    int st = g_start[bin];
    float4 v = make_float4(-FLT_MAX, -FLT_MAX, -FLT_MAX, -FLT_MAX);
    int i = 0;
    for (; i + 4 <= n; i += 4) {
        int p0 = g_sorted[st + i + 0];
        int p1 = g_sorted[st + i + 1];
        int p2 = g_sorted[st + i + 2];
        int p3 = g_sorted[st + i + 3];
        float4 a = *(const float4*)&g_net[(size_t)p0 * H + lane * 4];
        float4 b = *(const float4*)&g_net[(size_t)p1 * H + lane * 4];
        float4 c = *(const float4*)&g_net[(size_t)p2 * H + lane * 4];
        float4 d = *(const float4*)&g_net[(size_t)p3 * H + lane * 4];
        v = max4(v, max4(max4(a, b), max4(c, d)));
    }
    for (; i < n; i++) {
        int p = g_sorted[st + i];
        v = max4(v, *(const float4*)&g_net[(size_t)p * H + lane * 4]);
    }
    if (n > 0) *(float4*)&g_plane[(size_t)bin * H + lane * 4] = v;
}

// plane mean: warp-per-bin float4 gather + smem transpose + coalesced writes.
// grid = 24*128 = 3072, block 128 (4 warps, 8 bins per warp).
__global__ void __launch_bounds__(128)
mean_kernel(float* __restrict__ out) {
    __shared__ float tile[128][33];
    int pb = blockIdx.x >> 7;
    int r0 = (blockIdx.x & 127) * 32;
    int tid = threadIdx.x;
    int w = tid >> 5, lane = tid & 31;

    for (int g = 0; g < 8; g++) {
        int bb = g * 4 + w;
        int bin = pb * R2 + r0 + bb;
        int n = g_cnt[bin];
        int st = g_start[bin];
        float4 s = make_float4(0.f, 0.f, 0.f, 0.f);
        int i = 0;
        for (; i + 4 <= n; i += 4) {
            int p0 = g_sorted[st + i + 0];
            int p1 = g_sorted[st + i + 1];
            int p2 = g_sorted[st + i + 2];
            int p3 = g_sorted[st + i + 3];
            float4 a = *(const float4*)&g_c[(size_t)p0 * H + lane * 4];
            float4 b = *(const float4*)&g_c[(size_t)p1 * H + lane * 4];
            float4 c = *(const float4*)&g_c[(size_t)p2 * H + lane * 4];
            float4 d = *(const float4*)&g_c[(size_t)p3 * H + lane * 4];
            s.x += a.x + b.x + c.x + d.x;
            s.y += a.y + b.y + c.y + d.y;
            s.z += a.z + b.z + c.z + d.z;
            s.w += a.w + b.w + c.w + d.w;
        }
        for (; i < n; i++) {
            float4 a = *(const float4*)&g_c[(size_t)g_sorted[st + i] * H + lane * 4];
            s.x += a.x; s.y += a.y; s.z += a.z; s.w += a.w;
        }
        float inv = 1.0f / (float)max(n, 1);
        tile[lane * 4 + 0][bb] = s.x * inv;
        tile[lane * 4 + 1][bb] = s.y * inv;
        tile[lane * 4 + 2][bb] = s.z * inv;
        tile[lane * 4 + 3][bb] = s.w * inv;
    }
    __syncthreads();
    int rowq = tid >> 5;
    for (int it = 0; it < 32; it++) {
        int row = it * 4 + rowq;
        out[((size_t)pb * H + row) * R2 + r0 + lane] = tile[row][lane];
    }
}

extern "C" void kernel_launch(void* const* d_in, const int* in_sizes, int n_in,
                              void* d_out, int out_size) {
    const float* pts  = (const float*)d_in[0];
    const int*   ixz  = (const int*)d_in[1];
    const int*   ixy  = (const int*)d_in[2];
    const int*   iyz  = (const int*)d_in[3];
    const float* fcpw = (const float*)d_in[4];
    const float* fcpb = (const float*)d_in[5];
    const float* fc0w = (const float*)d_in[6];
    const float* fc0b = (const float*)d_in[7];
    const float* fc1w = (const float*)d_in[8];
    const float* fc1b = (const float*)d_in[9];
    const float* scw  = (const float*)d_in[10];
    const float* fccw = (const float*)d_in[11];
    const float* fccb = (const float*)d_in[12];
    float* out = (float*)d_out;

    cudaFuncSetAttribute(resnet_kernel, cudaFuncAttributeMaxDynamicSharedMemorySize, SMEM_SZ);
    cudaFuncSetAttribute(proj_kernel,   cudaFuncAttributeMaxDynamicSharedMemorySize, SMEM_SZ);

    prep_w_kernel<<<(WTOT + 255) / 256, 256>>>(fc0w, fc1w, scw, fccw);   // 0
    zero_meta_kernel<<<(CNTN + 255) / 256, 256>>>();                     // 1
    count_kernel<<<(NPTS + 255) / 256, 256>>>(ixz, ixy, iyz);            // 2
    // resnet block 0 at index 3 (ncu -s 5 lands here given 2 harness pre-launches)
    resnet_kernel<<<NTILES, 512, SMEM_SZ>>>(0, pts, ixz, ixy, iyz, fcpw, fcpb,
                                            0, fc0b, fc1b);              // 3
    scan1_kernel<<<96, 1024>>>();                                        // 4
    scan2_kernel<<<1, 128>>>();                                          // 5
    scan3_kernel<<<(CNTN + 255) / 256, 256>>>();                         // 6
    sortfill_kernel<<<(NPTS + 255) / 256, 256>>>(ixz, ixy, iyz);         // 7

    for (int it = 1; it < 5; it++) {
        pool_max_kernel<<<CNTN / 8, 256>>>();
        resnet_kernel<<<NTILES, 512, SMEM_SZ>>>(1, pts, ixz, ixy, iyz, fcpw, fcpb,
                                                it, fc0b + (size_t)it * H,
                                                fc1b + (size_t)it * H);
    }
    proj_kernel<<<NTILES, 512, SMEM_SZ>>>(fccb);
    mean_kernel<<<24 * 128, 128>>>(out);
}

// round 13
// speedup vs baseline: 1.2380x; 1.0044x over previous
#include <cuda_runtime.h>
#include <cuda_bf16.h>
#include <cfloat>
#include <cstdint>

#define BATCH 8
#define TPTS 30000
#define NPTS (BATCH*TPTS)
#define H 128
#define R2 4096
#define PTILE 128
#define NTILES (NPTS/PTILE)       // 1875
#define CNTN (3*BATCH*R2)

// transposed bf16 weight segments (element offsets): [out][k] K-major
#define W0OFF 0
#define SCOFF 163840
#define W1OFF 327680
#define WCOFF 409600
#define WTOT  425984

#define AS 264              // A row stride in bf16 (K=256 + 8 pad)
#define BSB 72              // B row stride in bf16 (K=64 chunk + 8 pad)

// smem byte layout (PTILE=128 rows)
#define SM_SBIN 0
#define SM_AH 2048
#define SM_AL (SM_AH + 128*AS*2)
#define SM_B  (SM_AL + 128*AS*2)          // 137216
#define HIB   (128*BSB*2)                  // 18432
#define BBUF  (2*HIB)                      // 36864
#define SMEM_SZ (SM_B + 2*BBUF)            // 210944 -> 1 CTA/SM

typedef unsigned short u16;

__device__ __align__(16) float g_net[(size_t)NPTS*H];
__device__ __align__(16) float g_c[(size_t)NPTS*H];
__device__ __align__(16) float g_plane[(size_t)CNTN*H];
__device__ __align__(16) __nv_bfloat16 g_whi[WTOT];
__device__ __align__(16) __nv_bfloat16 g_wlo[WTOT];
__device__ int g_cnt[CNTN], g_start[CNTN], g_cursor[CNTN];
__device__ int g_sorted[3*NPTS];
__device__ int g_bsum[96];

// ---------------- low-level helpers ----------------
__device__ __forceinline__ uint32_t smem_u32(const void* p) {
    uint32_t a;
    asm("{ .reg .u64 t; cvta.to.shared.u64 t, %1; cvt.u32.u64 %0, t; }" : "=r"(a) : "l"(p));
    return a;
}
__device__ __forceinline__ void cp16(uint32_t dst, const void* src) {
    asm volatile("cp.async.cg.shared.global [%0], [%1], 16;" :: "r"(dst), "l"(src));
}
#define CP_COMMIT() asm volatile("cp.async.commit_group;" ::: "memory")
#define CP_WAIT1()  asm volatile("cp.async.wait_group 1;" ::: "memory")
#define CP_WAIT0()  asm volatile("cp.async.wait_group 0;" ::: "memory")

__device__ __forceinline__ void ldmx4(uint32_t r[4], uint32_t addr) {
    asm volatile("ldmatrix.sync.aligned.m8n8.x4.shared.b16 {%0,%1,%2,%3}, [%4];"
        : "=r"(r[0]), "=r"(r[1]), "=r"(r[2]), "=r"(r[3]) : "r"(addr));
}
__device__ __forceinline__ void mma16816(float c[4], const uint32_t a[4], uint32_t b0, uint32_t b1) {
    asm volatile("mma.sync.aligned.m16n8k16.row.col.f32.bf16.bf16.f32 "
        "{%0,%1,%2,%3}, {%4,%5,%6,%7}, {%8,%9}, {%0,%1,%2,%3};"
        : "+f"(c[0]), "+f"(c[1]), "+f"(c[2]), "+f"(c[3])
        : "r"(a[0]), "r"(a[1]), "r"(a[2]), "r"(a[3]), "r"(b0), "r"(b1));
}

// bf16 split: v = hi + lo
__device__ __forceinline__ void dec2(float v, u16& h, u16& l) {
    __nv_bfloat16 hb = __float2bfloat16(v);
    float hf = __bfloat162float(hb);
    __nv_bfloat16 lb = __float2bfloat16(v - hf);
    h = *(u16*)&hb; l = *(u16*)&lb;
}
__device__ __forceinline__ uint32_t dec2pack(float v0, float v1, uint32_t& lop) {
    u16 h0, l0, h1, l1;
    dec2(v0, h0, l0); dec2(v1, h1, l1);
    lop = (uint32_t)l0 | ((uint32_t)l1 << 16);
    return (uint32_t)h0 | ((uint32_t)h1 << 16);
}

// exact relu on split fragments: sign(x) == sign(hi)
__device__ __forceinline__ void frag_relu(uint32_t ah[4], uint32_t al[4]) {
    __nv_bfloat162 z = __float2bfloat162_rn(0.f);
#pragma unroll
    for (int i = 0; i < 4; i++) {
        __nv_bfloat162 h = *(__nv_bfloat162*)&ah[i];
        __nv_bfloat162 l = *(__nv_bfloat162*)&al[i];
        __nv_bfloat162 m = __hgt2(h, z);
        h = __hmax2(h, z);
        l = __hmul2(l, m);
        ah[i] = *(uint32_t*)&h; al[i] = *(uint32_t*)&l;
    }
}

// ---------------- B chunk loader (K=64 chunk, hi+lo, 512 threads) ----------------
__device__ __forceinline__ void load_b(uint32_t smb, const __nv_bfloat16* __restrict__ wh,
                                       const __nv_bfloat16* __restrict__ wl,
                                       int K, int c, int buf, int tid) {
    int n = tid >> 2, qq = tid & 3;
    uint32_t d = smb + SM_B + buf * BBUF + n * (BSB * 2) + qq * 32;
    const __nv_bfloat16* sh = wh + (size_t)n * K + c * 64 + qq * 16;
    const __nv_bfloat16* sl = wl + (size_t)n * K + c * 64 + qq * 16;
    cp16(d, sh);            cp16(d + 16, sh + 8);
    cp16(d + HIB, sl);      cp16(d + HIB + 16, sl + 8);
    CP_COMMIT();
}

// ---------------- one K=64 chunk of MMA work (3-pass split) ----------------
template<bool RELU>
__device__ __forceinline__ void chunk_body(uint32_t smb, uint32_t bbh, uint32_t bbl,
                                           int kr0, float acc[2][4][4],
                                           int lane, int m0, int n0) {
#pragma unroll
    for (int ks = 0; ks < 4; ks++) {
        int kr = kr0 + ks * 16;
        uint32_t a_h[2][4], a_l[2][4];
#pragma unroll
        for (int mt = 0; mt < 2; mt++) {
            uint32_t off = (uint32_t)((m0 + mt * 16 + (lane & 15)) * AS + kr + ((lane >> 4) << 3)) * 2;
            ldmx4(a_h[mt], smb + SM_AH + off);
            ldmx4(a_l[mt], smb + SM_AL + off);
            if (RELU) frag_relu(a_h[mt], a_l[mt]);
        }
        uint32_t bh0[4], bh1[4], bl0[4], bl1[4];
#pragma unroll
        for (int np = 0; np < 2; np++) {
            uint32_t boff = (uint32_t)((n0 + np * 16 + (lane & 15)) * BSB + ks * 16 + ((lane >> 4) << 3)) * 2;
            uint32_t r[4];
            ldmx4(r, bbh + boff);
            bh0[2*np] = r[0]; bh0[2*np+1] = r[1]; bh1[2*np] = r[2]; bh1[2*np+1] = r[3];
            ldmx4(r, bbl + boff);
            bl0[2*np] = r[0]; bl0[2*np+1] = r[1]; bl1[2*np] = r[2]; bl1[2*np+1] = r[3];
        }
#pragma unroll
        for (int mt = 0; mt < 2; mt++)
#pragma unroll
            for (int nt = 0; nt < 4; nt++) mma16816(acc[mt][nt], a_h[mt], bh0[nt], bh1[nt]);
#pragma unroll
        for (int mt = 0; mt < 2; mt++)
#pragma unroll
            for (int nt = 0; nt < 4; nt++) mma16816(acc[mt][nt], a_l[mt], bh0[nt], bh1[nt]);
#pragma unroll
        for (int mt = 0; mt < 2; mt++)
#pragma unroll
            for (int nt = 0; nt < 4; nt++) mma16816(acc[mt][nt], a_h[mt], bl0[nt], bl1[nt]);
    }
}

__device__ __forceinline__ void zero_acc(float acc[2][4][4]) {
#pragma unroll
    for (int i = 0; i < 2; i++)
#pragma unroll
        for (int j = 0; j < 4; j++)
#pragma unroll
            for (int k = 0; k < 4; k++) acc[i][j][k] = 0.f;
}

// chunk schedule: which B segment + K + sub-chunk for global chunk index c
__device__ __forceinline__ void bsched(int c, const __nv_bfloat16* schi, const __nv_bfloat16* sclo,
                                       const __nv_bfloat16* w0hi, const __nv_bfloat16* w0lo,
                                       const __nv_bfloat16* w1hi, const __nv_bfloat16* w1lo,
                                       const __nv_bfloat16*& wh, const __nv_bfloat16*& wl,
                                       int& K, int& cc) {
    if (c < 4)       { wh = schi; wl = sclo; K = 256; cc = c; }
    else if (c < 8)  { wh = w0hi; wl = w0lo; K = 256; cc = c - 4; }
    else if (c < 10) { wh = w1hi; wl = w1lo; K = 128; cc = c - 8; }
    else             { wh = g_whi + WCOFF; wl = g_wlo + WCOFF; K = 128; cc = c - 10; }
}

// ---------------- fused resnet block (continuous pipeline; blk==4 fuses proj) ----------------
__global__ void __launch_bounds__(512, 1)
resnet_kernel(int mode,
              const float* __restrict__ pts,
              const int* __restrict__ ixz, const int* __restrict__ ixy,
              const int* __restrict__ iyz,
              const float* __restrict__ fcpw, const float* __restrict__ fcpb,
              int blk,
              const float* __restrict__ fc0b, const float* __restrict__ fc1b,
              const float* __restrict__ bc) {
    extern __shared__ char smem[];
    uint32_t smb = smem_u32(smem);
    int tid = threadIdx.x;
    int lane = tid & 31, wid = tid >> 5;
    int m0 = (wid >> 2) * 32, n0 = (wid & 3) * 32;
    int pbase = blockIdx.x * PTILE;
    int* sbin = (int*)(smem + SM_SBIN);
    const int fuse = (blk == 4);
    const int NC = fuse ? 12 : 10;

    const __nv_bfloat16* w0hi = g_whi + W0OFF + (size_t)blk * 32768;
    const __nv_bfloat16* w0lo = g_wlo + W0OFF + (size_t)blk * 32768;
    const __nv_bfloat16* schi = g_whi + SCOFF + (size_t)blk * 32768;
    const __nv_bfloat16* sclo = g_wlo + SCOFF + (size_t)blk * 32768;
    const __nv_bfloat16* w1hi = g_whi + W1OFF + (size_t)blk * 16384;
    const __nv_bfloat16* w1lo = g_wlo + W1OFF + (size_t)blk * 16384;

    // prime chunk 0 (shortcut B) so DMA overlaps the A fill
    load_b(smb, schi, sclo, 256, 0, 0, tid);

    if (mode == 1 && tid < PTILE) {
        int gp = pbase + tid;
        int b = gp / TPTS;
        sbin[tid]             = (0 * BATCH + b) * R2 + ixz[gp];
        sbin[PTILE + tid]     = (1 * BATCH + b) * R2 + ixy[gp];
        sbin[2 * PTILE + tid] = (2 * BATCH + b) * R2 + iyz[gp];
    }
    __syncthreads();

    // ---- fill A (x) hi/lo ----
    {
        int k = tid & 255;
        int s0 = (tid >> 8) * 64;
        u16* ah = (u16*)(smem + SM_AH) + k;
        u16* al = (u16*)(smem + SM_AL) + k;
        if (mode == 0) {
            float wk0 = fcpw[k], wk1 = fcpw[256 + k], wk2 = fcpw[512 + k];
            float bk = fcpb[k];
            for (int s = s0; s < s0 + 64; s++) {
                int gp = pbase + s;
                float v = bk + pts[gp*3]*wk0 + pts[gp*3+1]*wk1 + pts[gp*3+2]*wk2;
                u16 h, l; dec2(v, h, l);
                ah[s * AS] = h; al[s * AS] = l;
            }
        } else if (k < H) {
            for (int s = s0; s < s0 + 64; s++) {
                float v = g_net[(size_t)(pbase + s) * H + k];
                u16 h, l; dec2(v, h, l);
                ah[s * AS] = h; al[s * AS] = l;
            }
        } else {
            int ch = k - H;
            for (int s = s0; s < s0 + 64; s++) {
                float v = g_plane[(size_t)sbin[s] * H + ch]
                        + g_plane[(size_t)sbin[PTILE + s] * H + ch]
                        + g_plane[(size_t)sbin[2 * PTILE + s] * H + ch];
                u16 h, l; dec2(v, h, l);
                ah[s * AS] = h; al[s * AS] = l;
            }
        }
    }

    float acc_sc[2][4][4], accB[2][4][4];
    zero_acc(acc_sc);
    zero_acc(accB);

    // ---- continuous chunk pipeline ----
    for (int c = 0; c < NC; c++) {
        if (c + 1 < NC) {
            const __nv_bfloat16 *nwh, *nwl; int nK, ncc;
            bsched(c + 1, schi, sclo, w0hi, w0lo, w1hi, w1lo, nwh, nwl, nK, ncc);
            load_b(smb, nwh, nwl, nK, ncc, (c + 1) & 1, tid);
            CP_WAIT1();
        } else CP_WAIT0();
        __syncthreads();

        if (c == 8) {
            // epilogue1: ns = relu(accB + b0) -> A region cols 0..127 (hi/lo)
#pragma unroll
            for (int mt = 0; mt < 2; mt++)
#pragma unroll
                for (int nt = 0; nt < 4; nt++) {
                    int row = m0 + mt * 16 + (lane >> 2);
                    int col = n0 + nt * 8 + (lane & 3) * 2;
                    float ba = fc0b[col], bb = fc0b[col + 1];
                    uint32_t lo, hi;
                    hi = dec2pack(fmaxf(accB[mt][nt][0] + ba, 0.f), fmaxf(accB[mt][nt][1] + bb, 0.f), lo);
                    *(uint32_t*)(smem + SM_AH + (row * AS + col) * 2) = hi;
                    *(uint32_t*)(smem + SM_AL + (row * AS + col) * 2) = lo;
                    hi = dec2pack(fmaxf(accB[mt][nt][2] + ba, 0.f), fmaxf(accB[mt][nt][3] + bb, 0.f), lo);
                    *(uint32_t*)(smem + SM_AH + ((row + 8) * AS + col) * 2) = hi;
                    *(uint32_t*)(smem + SM_AL + ((row + 8) * AS + col) * 2) = lo;
                }
            __syncthreads();
        }
        if (c == 10) {
            // epilogue2A (fused proj): out = acc_sc + b1 -> A region; reset accB for proj
#pragma unroll
            for (int mt = 0; mt < 2; mt++)
#pragma unroll
                for (int nt = 0; nt < 4; nt++) {
                    int row = m0 + mt * 16 + (lane >> 2);
                    int col = n0 + nt * 8 + (lane & 3) * 2;
                    float ba = fc1b[col], bb = fc1b[col + 1];
                    uint32_t lo, hi;
                    hi = dec2pack(acc_sc[mt][nt][0] + ba, acc_sc[mt][nt][1] + bb, lo);
                    *(uint32_t*)(smem + SM_AH + (row * AS + col) * 2) = hi;
                    *(uint32_t*)(smem + SM_AL + (row * AS + col) * 2) = lo;
                    hi = dec2pack(acc_sc[mt][nt][2] + ba, acc_sc[mt][nt][3] + bb, lo);
                    *(uint32_t*)(smem + SM_AH + ((row + 8) * AS + col) * 2) = hi;
                    *(uint32_t*)(smem + SM_AL + ((row + 8) * AS + col) * 2) = lo;
                }
            zero_acc(accB);
            __syncthreads();
        }

        uint32_t bbh = smb + SM_B + (c & 1) * BBUF;
        uint32_t bbl = bbh + HIB;
        int kr0 = ((c < 4) ? c : (c < 8) ? (c - 4) : (c < 10) ? (c - 8) : (c - 10)) * 64;

        if (c < 4 || c == 8 || c == 9)
            chunk_body<false>(smb, bbh, bbl, kr0, acc_sc, lane, m0, n0);
        else if (c < 8)
            chunk_body<true>(smb, bbh, bbl, kr0, accB, lane, m0, n0);
        else
            chunk_body<false>(smb, bbh, bbl, kr0, accB, lane, m0, n0);

        __syncthreads();
    }

    // ---- final epilogue ----
    if (!fuse) {
        // g_net = acc_sc + b1
#pragma unroll
        for (int mt = 0; mt < 2; mt++)
#pragma unroll
            for (int nt = 0; nt < 4; nt++) {
                int row = pbase + m0 + mt * 16 + (lane >> 2);
                int col = n0 + nt * 8 + (lane & 3) * 2;
                float ba = fc1b[col], bb = fc1b[col + 1];
                *(float2*)&g_net[(size_t)row * H + col] =
                    make_float2(acc_sc[mt][nt][0] + ba, acc_sc[mt][nt][1] + bb);
                *(float2*)&g_net[(size_t)(row + 8) * H + col] =
                    make_float2(acc_sc[mt][nt][2] + ba, acc_sc[mt][nt][3] + bb);
            }
    } else {
        // g_c = accB (proj result) + bc
#pragma unroll
        for (int mt = 0; mt < 2; mt++)
#pragma unroll
            for (int nt = 0; nt < 4; nt++) {
                int row = pbase + m0 + mt * 16 + (lane >> 2);
                int col = n0 + nt * 8 + (lane & 3) * 2;
                float ba = bc[col], bb = bc[col + 1];
                *(float2*)&g_c[(size_t)row * H + col] =
                    make_float2(accB[mt][nt][0] + ba, accB[mt][nt][1] + bb);
                *(float2*)&g_c[(size_t)(row + 8) * H + col] =
                    make_float2(accB[mt][nt][2] + ba, accB[mt][nt][3] + bb);
            }
    }
}

// ---------------- weight prep: transpose + hi/lo decompose ----------------
__global__ void prep_w_kernel(const float* __restrict__ fc0w, const float* __restrict__ fc1w,
                              const float* __restrict__ scw,  const float* __restrict__ fccw) {
    int idx = blockIdx.x * 256 + threadIdx.x;
    if (idx >= WTOT) return;
    float v;
    if (idx < SCOFF) {
        int blk = idx >> 15, r = idx & 32767, out = r >> 8, k = r & 255;
        v = fc0w[((size_t)blk * 256 + k) * 128 + out];
    } else if (idx < W1OFF) {
        int i = idx - SCOFF;
        int blk = i >> 15, r = i & 32767, out = r >> 8, k = r & 255;
        v = scw[((size_t)blk * 256 + k) * 128 + out];
    } else if (idx < WCOFF) {
        int i = idx - W1OFF;
        int blk = i >> 14, r = i & 16383, out = r >> 7, k = r & 127;
        v = fc1w[((size_t)blk * 128 + k) * 128 + out];
    } else {
        int i = idx - WCOFF;
        int out = i >> 7, k = i & 127;
        v = fccw[(size_t)k * 128 + out];
    }
    u16 h, l; dec2(v, h, l);
    g_whi[idx] = *(__nv_bfloat16*)&h;
    g_wlo[idx] = *(__nv_bfloat16*)&l;
}

// ============ sorted-bin infrastructure ============
__global__ void zero_meta_kernel() {
    int i = blockIdx.x * 256 + threadIdx.x;
    if (i < CNTN) { g_cnt[i] = 0; g_cursor[i] = 0; }
}

__global__ void count_kernel(const int* __restrict__ ixz, const int* __restrict__ ixy,
                             const int* __restrict__ iyz) {
    int p = blockIdx.x * 256 + threadIdx.x;
    if (p >= NPTS) return;
    int b = p / TPTS;
    atomicAdd(&g_cnt[(0 * BATCH + b) * R2 + ixz[p]], 1);
    atomicAdd(&g_cnt[(1 * BATCH + b) * R2 + ixy[p]], 1);
    atomicAdd(&g_cnt[(2 * BATCH + b) * R2 + iyz[p]], 1);
}

__global__ void scan1_kernel() {
    __shared__ int smv[1024];
    int tid = threadIdx.x;
    int i = blockIdx.x * 1024 + tid;
    int v = g_cnt[i];
    smv[tid] = v;
    __syncthreads();
    for (int off = 1; off < 1024; off <<= 1) {
        int t = 0;
        if (tid >= off) t = smv[tid - off];
        __syncthreads();
        if (tid >= off) smv[tid] += t;
        __syncthreads();
    }
    g_start[i] = smv[tid] - v;
    if (tid == 1023) g_bsum[blockIdx.x] = smv[tid];
}

__global__ void scan2_kernel() {
    __shared__ int smv[128];
    int tid = threadIdx.x;
    int v = (tid < 96) ? g_bsum[tid] : 0;
    smv[tid] = v;
    __syncthreads();
    for (int off = 1; off < 128; off <<= 1) {
        int t = 0;
        if (tid >= off) t = smv[tid - off];
        __syncthreads();
        if (tid >= off) smv[tid] += t;
        __syncthreads();
    }
    if (tid < 96) g_bsum[tid] = smv[tid] - v;
}

__global__ void scan3_kernel() {
    int i = blockIdx.x * 256 + threadIdx.x;
    if (i < CNTN) g_start[i] += g_bsum[i >> 10];
}

__global__ void sortfill_kernel(const int* __restrict__ ixz, const int* __restrict__ ixy,
                                const int* __restrict__ iyz) {
    int p = blockIdx.x * 256 + threadIdx.x;
    if (p >= NPTS) return;
    int b = p / TPTS;
    int bins[3];
    bins[0] = (0 * BATCH + b) * R2 + ixz[p];
    bins[1] = (1 * BATCH + b) * R2 + ixy[p];
    bins[2] = (2 * BATCH + b) * R2 + iyz[p];
#pragma unroll
    for (int pl = 0; pl < 3; pl++) {
        int pos = atomicAdd(&g_cursor[bins[pl]], 1);
        g_sorted[g_start[bins[pl]] + pos] = p;
    }
}

__device__ __forceinline__ float4 max4(float4 a, float4 b) {
    return make_float4(fmaxf(a.x, b.x), fmaxf(a.y, b.y), fmaxf(a.z, b.z), fmaxf(a.w, b.w));
}

// pool max: warp-per-bin, float4 channels. grid = CNTN/8, block 256.
__global__ void __launch_bounds__(256)
pool_max_kernel() {
    int w = threadIdx.x >> 5, lane = threadIdx.x & 31;
    int bin = blockIdx.x * 8 + w;
    int n = g_cnt[bin];
    int st = g_start[bin];
    float4 v = make_float4(-FLT_MAX, -FLT_MAX, -FLT_MAX, -FLT_MAX);
    int i = 0;
    for (; i + 4 <= n; i += 4) {
        int p0 = g_sorted[st + i + 0];
        int p1 = g_sorted[st + i + 1];
        int p2 = g_sorted[st + i + 2];
        int p3 = g_sorted[st + i + 3];
        float4 a = *(const float4*)&g_net[(size_t)p0 * H + lane * 4];
        float4 b = *(const float4*)&g_net[(size_t)p1 * H + lane * 4];
        float4 c = *(const float4*)&g_net[(size_t)p2 * H + lane * 4];
        float4 d = *(const float4*)&g_net[(size_t)p3 * H + lane * 4];
        v = max4(v, max4(max4(a, b), max4(c, d)));
    }
    for (; i < n; i++) {
        int p = g_sorted[st + i];
        v = max4(v, *(const float4*)&g_net[(size_t)p * H + lane * 4]);
    }
    if (n > 0) *(float4*)&g_plane[(size_t)bin * H + lane * 4] = v;
}

// plane mean: warp-per-bin float4 gather + smem transpose + coalesced writes.
__global__ void __launch_bounds__(128)
mean_kernel(float* __restrict__ out) {
    __shared__ float tile[128][33];
    int pb = blockIdx.x >> 7;
    int r0 = (blockIdx.x & 127) * 32;
    int tid = threadIdx.x;
    int w = tid >> 5, lane = tid & 31;

    for (int g = 0; g < 8; g++) {
        int bb = g * 4 + w;
        int bin = pb * R2 + r0 + bb;
        int n = g_cnt[bin];
        int st = g_start[bin];
        float4 s = make_float4(0.f, 0.f, 0.f, 0.f);
        int i = 0;
        for (; i + 4 <= n; i += 4) {
            int p0 = g_sorted[st + i + 0];
            int p1 = g_sorted[st + i + 1];
            int p2 = g_sorted[st + i + 2];
            int p3 = g_sorted[st + i + 3];
            float4 a = *(const float4*)&g_c[(size_t)p0 * H + lane * 4];
            float4 b = *(const float4*)&g_c[(size_t)p1 * H + lane * 4];
            float4 c = *(const float4*)&g_c[(size_t)p2 * H + lane * 4];
            float4 d = *(const float4*)&g_c[(size_t)p3 * H + lane * 4];
            s.x += a.x + b.x + c.x + d.x;
            s.y += a.y + b.y + c.y + d.y;
            s.z += a.z + b.z + c.z + d.z;
            s.w += a.w + b.w + c.w + d.w;
        }
        for (; i < n; i++) {
            float4 a = *(const float4*)&g_c[(size_t)g_sorted[st + i] * H + lane * 4];
            s.x += a.x; s.y += a.y; s.z += a.z; s.w += a.w;
        }
        float inv = 1.0f / (float)max(n, 1);
        tile[lane * 4 + 0][bb] = s.x * inv;
        tile[lane * 4 + 1][bb] = s.y * inv;
        tile[lane * 4 + 2][bb] = s.z * inv;
        tile[lane * 4 + 3][bb] = s.w * inv;
    }
    __syncthreads();
    int rowq = tid >> 5;
    for (int it = 0; it < 32; it++) {
        int row = it * 4 + rowq;
        out[((size_t)pb * H + row) * R2 + r0 + lane] = tile[row][lane];
    }
}

extern "C" void kernel_launch(void* const* d_in, const int* in_sizes, int n_in,
                              void* d_out, int out_size) {
    const float* pts  = (const float*)d_in[0];
    const int*   ixz  = (const int*)d_in[1];
    const int*   ixy  = (const int*)d_in[2];
    const int*   iyz  = (const int*)d_in[3];
    const float* fcpw = (const float*)d_in[4];
    const float* fcpb = (const float*)d_in[5];
    const float* fc0w = (const float*)d_in[6];
    const float* fc0b = (const float*)d_in[7];
    const float* fc1w = (const float*)d_in[8];
    const float* fc1b = (const float*)d_in[9];
    const float* scw  = (const float*)d_in[10];
    const float* fccw = (const float*)d_in[11];
    const float* fccb = (const float*)d_in[12];
    float* out = (float*)d_out;

    cudaFuncSetAttribute(resnet_kernel, cudaFuncAttributeMaxDynamicSharedMemorySize, SMEM_SZ);

    prep_w_kernel<<<(WTOT + 255) / 256, 256>>>(fc0w, fc1w, scw, fccw);   // 0
    zero_meta_kernel<<<(CNTN + 255) / 256, 256>>>();                     // 1
    count_kernel<<<(NPTS + 255) / 256, 256>>>(ixz, ixy, iyz);            // 2
    // resnet block 0 at index 3 (ncu -s 5 lands here)
    resnet_kernel<<<NTILES, 512, SMEM_SZ>>>(0, pts, ixz, ixy, iyz, fcpw, fcpb,
                                            0, fc0b, fc1b, fccb);        // 3
    scan1_kernel<<<96, 1024>>>();                                        // 4
    scan2_kernel<<<1, 128>>>();                                          // 5
    scan3_kernel<<<(CNTN + 255) / 256, 256>>>();                         // 6
    sortfill_kernel<<<(NPTS + 255) / 256, 256>>>(ixz, ixy, iyz);         // 7

    for (int it = 1; it < 5; it++) {
        pool_max_kernel<<<CNTN / 8, 256>>>();
        resnet_kernel<<<NTILES, 512, SMEM_SZ>>>(1, pts, ixz, ixy, iyz, fcpw, fcpb,
                                                it, fc0b + (size_t)it * H,
                                                fc1b + (size_t)it * H, fccb);
    }
    mean_kernel<<<24 * 128, 128>>>(out);
}

// round 14
// speedup vs baseline: 1.5756x; 1.2727x over previous
#include <cuda_runtime.h>
#include <cuda_fp16.h>
#include <cfloat>
#include <cstdint>

#define BATCH 8
#define TPTS 30000
#define NPTS (BATCH*TPTS)
#define H 128
#define R2 4096
#define PTILE 128
#define NTILES (NPTS/PTILE)       // 1875
#define CNTN (3*BATCH*R2)

// transposed fp16 weight segments (element offsets): [out][k] K-major
#define W0OFF 0
#define SCOFF 163840
#define W1OFF 327680
#define WCOFF 409600
#define WTOT  425984

#define AS 264              // A row stride in fp16 (K=256 + 8 pad)
#define BSB 72              // B row stride in fp16 (K=64 chunk + 8 pad)

// smem byte layout (PTILE=128 rows)
#define SM_SBIN 0
#define SM_AH 2048
#define SM_AL (SM_AH + 128*AS*2)
#define SM_B  (SM_AL + 128*AS*2)          // 137216
#define BBUF  (128*BSB*2)                  // 18432 (single-precision-level B: fp16 hi only)
#define SMEM_SZ (SM_B + 2*BBUF)            // 174080 -> 1 CTA/SM

typedef unsigned short u16;

__device__ __align__(16) float g_net[(size_t)NPTS*H];
__device__ __align__(16) float g_c[(size_t)NPTS*H];
__device__ __align__(16) float g_plane[(size_t)CNTN*H];
__device__ __align__(16) __half g_w[WTOT];
__device__ int g_cnt[CNTN], g_start[CNTN], g_cursor[CNTN];
__device__ int g_sorted[3*NPTS];
__device__ int g_bsum[96];

// ---------------- low-level helpers ----------------
__device__ __forceinline__ uint32_t smem_u32(const void* p) {
    uint32_t a;
    asm("{ .reg .u64 t; cvta.to.shared.u64 t, %1; cvt.u32.u64 %0, t; }" : "=r"(a) : "l"(p));
    return a;
}
__device__ __forceinline__ void cp16(uint32_t dst, const void* src) {
    asm volatile("cp.async.cg.shared.global [%0], [%1], 16;" :: "r"(dst), "l"(src));
}
#define CP_COMMIT() asm volatile("cp.async.commit_group;" ::: "memory")
#define CP_WAIT1()  asm volatile("cp.async.wait_group 1;" ::: "memory")
#define CP_WAIT0()  asm volatile("cp.async.wait_group 0;" ::: "memory")

__device__ __forceinline__ void ldmx4(uint32_t r[4], uint32_t addr) {
    asm volatile("ldmatrix.sync.aligned.m8n8.x4.shared.b16 {%0,%1,%2,%3}, [%4];"
        : "=r"(r[0]), "=r"(r[1]), "=r"(r[2]), "=r"(r[3]) : "r"(addr));
}
__device__ __forceinline__ void mma16816(float c[4], const uint32_t a[4], uint32_t b0, uint32_t b1) {
    asm volatile("mma.sync.aligned.m16n8k16.row.col.f32.f16.f16.f32 "
        "{%0,%1,%2,%3}, {%4,%5,%6,%7}, {%8,%9}, {%0,%1,%2,%3};"
        : "+f"(c[0]), "+f"(c[1]), "+f"(c[2]), "+f"(c[3])
        : "r"(a[0]), "r"(a[1]), "r"(a[2]), "r"(a[3]), "r"(b0), "r"(b1));
}

// fp16 split: v = hi + lo (hi = rn(v), lo = rn(v-hi)); ~22 bits total
__device__ __forceinline__ void dec2h(float v, u16& h, u16& l) {
    __half hb = __float2half_rn(v);
    float hf = __half2float(hb);
    __half lb = __float2half_rn(v - hf);
    h = *(u16*)&hb; l = *(u16*)&lb;
}
__device__ __forceinline__ uint32_t dec2packh(float v0, float v1, uint32_t& lop) {
    __half h0 = __float2half_rn(v0), h1 = __float2half_rn(v1);
    __half l0 = __float2half_rn(v0 - __half2float(h0));
    __half l1 = __float2half_rn(v1 - __half2float(h1));
    __half2 hp = __halves2half2(h0, h1);
    __half2 lp = __halves2half2(l0, l1);
    lop = *(uint32_t*)&lp;
    return *(uint32_t*)&hp;
}

// exact relu on split fragments: sign(v) == sign(hi)
__device__ __forceinline__ void frag_relu(uint32_t ah[4], uint32_t al[4]) {
    __half2 z = __floats2half2_rn(0.f, 0.f);
#pragma unroll
    for (int i = 0; i < 4; i++) {
        __half2 h = *(__half2*)&ah[i];
        __half2 l = *(__half2*)&al[i];
        __half2 m = __hgt2(h, z);
        h = __hmax2(h, z);
        l = __hmul2(l, m);
        ah[i] = *(uint32_t*)&h; al[i] = *(uint32_t*)&l;
    }
}

// ---------------- B chunk loader (K=64 chunk, fp16, 512 threads) ----------------
__device__ __forceinline__ void load_b(uint32_t smb, const __half* __restrict__ w,
                                       int K, int c, int buf, int tid) {
    int n = tid >> 2, qq = tid & 3;
    uint32_t d = smb + SM_B + buf * BBUF + n * (BSB * 2) + qq * 32;
    const __half* s = w + (size_t)n * K + c * 64 + qq * 16;
    cp16(d, s);
    cp16(d + 16, s + 8);
    CP_COMMIT();
}

// ---------------- one K=64 chunk of MMA work (2-pass fp16 split) ----------------
template<bool RELU>
__device__ __forceinline__ void chunk_body(uint32_t smb, uint32_t bbh,
                                           int kr0, float acc[2][4][4],
                                           int lane, int m0, int n0) {
#pragma unroll
    for (int ks = 0; ks < 4; ks++) {
        int kr = kr0 + ks * 16;
        uint32_t a_h[2][4], a_l[2][4];
#pragma unroll
        for (int mt = 0; mt < 2; mt++) {
            uint32_t off = (uint32_t)((m0 + mt * 16 + (lane & 15)) * AS + kr + ((lane >> 4) << 3)) * 2;
            ldmx4(a_h[mt], smb + SM_AH + off);
            ldmx4(a_l[mt], smb + SM_AL + off);
            if (RELU) frag_relu(a_h[mt], a_l[mt]);
        }
        uint32_t b0[4], b1[4];
#pragma unroll
        for (int np = 0; np < 2; np++) {
            uint32_t boff = (uint32_t)((n0 + np * 16 + (lane & 15)) * BSB + ks * 16 + ((lane >> 4) << 3)) * 2;
            uint32_t r[4];
            ldmx4(r, bbh + boff);
            b0[2*np] = r[0]; b0[2*np+1] = r[1]; b1[2*np] = r[2]; b1[2*np+1] = r[3];
        }
#pragma unroll
        for (int mt = 0; mt < 2; mt++)
#pragma unroll
            for (int nt = 0; nt < 4; nt++) mma16816(acc[mt][nt], a_h[mt], b0[nt], b1[nt]);
#pragma unroll
        for (int mt = 0; mt < 2; mt++)
#pragma unroll
            for (int nt = 0; nt < 4; nt++) mma16816(acc[mt][nt], a_l[mt], b0[nt], b1[nt]);
    }
}

__device__ __forceinline__ void zero_acc(float acc[2][4][4]) {
#pragma unroll
    for (int i = 0; i < 2; i++)
#pragma unroll
        for (int j = 0; j < 4; j++)
#pragma unroll
            for (int k = 0; k < 4; k++) acc[i][j][k] = 0.f;
}

// chunk schedule: which B segment + K + sub-chunk for global chunk index c
__device__ __forceinline__ void bsched(int c, const __half* sc, const __half* w0,
                                       const __half* w1,
                                       const __half*& w, int& K, int& cc) {
    if (c < 4)       { w = sc; K = 256; cc = c; }
    else if (c < 8)  { w = w0; K = 256; cc = c - 4; }
    else if (c < 10) { w = w1; K = 128; cc = c - 8; }
    else             { w = g_w + WCOFF; K = 128; cc = c - 10; }
}

// ---------------- fused resnet block (continuous pipeline; blk==4 fuses proj) ----------------
__global__ void __launch_bounds__(512, 1)
resnet_kernel(int mode,
              const float* __restrict__ pts,
              const int* __restrict__ ixz, const int* __restrict__ ixy,
              const int* __restrict__ iyz,
              const float* __restrict__ fcpw, const float* __restrict__ fcpb,
              int blk,
              const float* __restrict__ fc0b, const float* __restrict__ fc1b,
              const float* __restrict__ bc) {
    extern __shared__ char smem[];
    uint32_t smb = smem_u32(smem);
    int tid = threadIdx.x;
    int lane = tid & 31, wid = tid >> 5;
    int m0 = (wid >> 2) * 32, n0 = (wid & 3) * 32;
    int pbase = blockIdx.x * PTILE;
    int* sbin = (int*)(smem + SM_SBIN);
    const int fuse = (blk == 4);
    const int NC = fuse ? 12 : 10;

    const __half* w0 = g_w + W0OFF + (size_t)blk * 32768;
    const __half* sc = g_w + SCOFF + (size_t)blk * 32768;
    const __half* w1 = g_w + W1OFF + (size_t)blk * 16384;

    // prime chunk 0 (shortcut B) so DMA overlaps the A fill
    load_b(smb, sc, 256, 0, 0, tid);

    if (mode == 1 && tid < PTILE) {
        int gp = pbase + tid;
        int b = gp / TPTS;
        sbin[tid]             = (0 * BATCH + b) * R2 + ixz[gp];
        sbin[PTILE + tid]     = (1 * BATCH + b) * R2 + ixy[gp];
        sbin[2 * PTILE + tid] = (2 * BATCH + b) * R2 + iyz[gp];
    }
    __syncthreads();

    // ---- fill A (x) hi/lo ----
    {
        int k = tid & 255;
        int s0 = (tid >> 8) * 64;
        u16* ah = (u16*)(smem + SM_AH) + k;
        u16* al = (u16*)(smem + SM_AL) + k;
        if (mode == 0) {
            float wk0 = fcpw[k], wk1 = fcpw[256 + k], wk2 = fcpw[512 + k];
            float bk = fcpb[k];
            for (int s = s0; s < s0 + 64; s++) {
                int gp = pbase + s;
                float v = bk + pts[gp*3]*wk0 + pts[gp*3+1]*wk1 + pts[gp*3+2]*wk2;
                u16 h, l; dec2h(v, h, l);
                ah[s * AS] = h; al[s * AS] = l;
            }
        } else if (k < H) {
            for (int s = s0; s < s0 + 64; s++) {
                float v = g_net[(size_t)(pbase + s) * H + k];
                u16 h, l; dec2h(v, h, l);
                ah[s * AS] = h; al[s * AS] = l;
            }
        } else {
            int ch = k - H;
            for (int s = s0; s < s0 + 64; s++) {
                float v = g_plane[(size_t)sbin[s] * H + ch]
                        + g_plane[(size_t)sbin[PTILE + s] * H + ch]
                        + g_plane[(size_t)sbin[2 * PTILE + s] * H + ch];
                u16 h, l; dec2h(v, h, l);
                ah[s * AS] = h; al[s * AS] = l;
            }
        }
    }

    float acc_sc[2][4][4], accB[2][4][4];
    zero_acc(acc_sc);
    zero_acc(accB);

    // ---- continuous chunk pipeline ----
    for (int c = 0; c < NC; c++) {
        if (c + 1 < NC) {
            const __half* nw; int nK, ncc;
            bsched(c + 1, sc, w0, w1, nw, nK, ncc);
            load_b(smb, nw, nK, ncc, (c + 1) & 1, tid);
            CP_WAIT1();
        } else CP_WAIT0();
        __syncthreads();

        if (c == 8) {
            // epilogue1: ns = relu(accB + b0) -> A region cols 0..127 (hi/lo)
#pragma unroll
            for (int mt = 0; mt < 2; mt++)
#pragma unroll
                for (int nt = 0; nt < 4; nt++) {
                    int row = m0 + mt * 16 + (lane >> 2);
                    int col = n0 + nt * 8 + (lane & 3) * 2;
                    float ba = fc0b[col], bb = fc0b[col + 1];
                    uint32_t lo, hi;
                    hi = dec2packh(fmaxf(accB[mt][nt][0] + ba, 0.f), fmaxf(accB[mt][nt][1] + bb, 0.f), lo);
                    *(uint32_t*)(smem + SM_AH + (row * AS + col) * 2) = hi;
                    *(uint32_t*)(smem + SM_AL + (row * AS + col) * 2) = lo;
                    hi = dec2packh(fmaxf(accB[mt][nt][2] + ba, 0.f), fmaxf(accB[mt][nt][3] + bb, 0.f), lo);
                    *(uint32_t*)(smem + SM_AH + ((row + 8) * AS + col) * 2) = hi;
                    *(uint32_t*)(smem + SM_AL + ((row + 8) * AS + col) * 2) = lo;
                }
            __syncthreads();
        }
        if (c == 10) {
            // epilogue2A (fused proj): out = acc_sc + b1 -> A region; reset accB for proj
#pragma unroll
            for (int mt = 0; mt < 2; mt++)
#pragma unroll
                for (int nt = 0; nt < 4; nt++) {
                    int row = m0 + mt * 16 + (lane >> 2);
                    int col = n0 + nt * 8 + (lane & 3) * 2;
                    float ba = fc1b[col], bb = fc1b[col + 1];
                    uint32_t lo, hi;
                    hi = dec2packh(acc_sc[mt][nt][0] + ba, acc_sc[mt][nt][1] + bb, lo);
                    *(uint32_t*)(smem + SM_AH + (row * AS + col) * 2) = hi;
                    *(uint32_t*)(smem + SM_AL + (row * AS + col) * 2) = lo;
                    hi = dec2packh(acc_sc[mt][nt][2] + ba, acc_sc[mt][nt][3] + bb, lo);
                    *(uint32_t*)(smem + SM_AH + ((row + 8) * AS + col) * 2) = hi;
                    *(uint32_t*)(smem + SM_AL + ((row + 8) * AS + col) * 2) = lo;
                }
            zero_acc(accB);
            __syncthreads();
        }

        uint32_t bbh = smb + SM_B + (c & 1) * BBUF;
        int kr0 = ((c < 4) ? c : (c < 8) ? (c - 4) : (c < 10) ? (c - 8) : (c - 10)) * 64;

        if (c < 4 || c == 8 || c == 9)
            chunk_body<false>(smb, bbh, kr0, acc_sc, lane, m0, n0);
        else if (c < 8)
            chunk_body<true>(smb, bbh, kr0, accB, lane, m0, n0);
        else
            chunk_body<false>(smb, bbh, kr0, accB, lane, m0, n0);

        __syncthreads();
    }

    // ---- final epilogue ----
    if (!fuse) {
        // g_net = acc_sc + b1
#pragma unroll
        for (int mt = 0; mt < 2; mt++)
#pragma unroll
            for (int nt = 0; nt < 4; nt++) {
                int row = pbase + m0 + mt * 16 + (lane >> 2);
                int col = n0 + nt * 8 + (lane & 3) * 2;
                float ba = fc1b[col], bb = fc1b[col + 1];
                *(float2*)&g_net[(size_t)row * H + col] =
                    make_float2(acc_sc[mt][nt][0] + ba, acc_sc[mt][nt][1] + bb);
                *(float2*)&g_net[(size_t)(row + 8) * H + col] =
                    make_float2(acc_sc[mt][nt][2] + ba, acc_sc[mt][nt][3] + bb);
            }
    } else {
        // g_c = accB (proj result) + bc
#pragma unroll
        for (int mt = 0; mt < 2; mt++)
#pragma unroll
            for (int nt = 0; nt < 4; nt++) {
                int row = pbase + m0 + mt * 16 + (lane >> 2);
                int col = n0 + nt * 8 + (lane & 3) * 2;
                float ba = bc[col], bb = bc[col + 1];
                *(float2*)&g_c[(size_t)row * H + col] =
                    make_float2(accB[mt][nt][0] + ba, accB[mt][nt][1] + bb);
                *(float2*)&g_c[(size_t)(row + 8) * H + col] =
                    make_float2(accB[mt][nt][2] + ba, accB[mt][nt][3] + bb);
            }
    }
}

// ---------------- weight prep: transpose + fp16 ----------------
__global__ void prep_w_kernel(const float* __restrict__ fc0w, const float* __restrict__ fc1w,
                              const float* __restrict__ scw,  const float* __restrict__ fccw) {
    int idx = blockIdx.x * 256 + threadIdx.x;
    if (idx >= WTOT) return;
    float v;
    if (idx < SCOFF) {
        int blk = idx >> 15, r = idx & 32767, out = r >> 8, k = r & 255;
        v = fc0w[((size_t)blk * 256 + k) * 128 + out];
    } else if (idx < W1OFF) {
        int i = idx - SCOFF;
        int blk = i >> 15, r = i & 32767, out = r >> 8, k = r & 255;
        v = scw[((size_t)blk * 256 + k) * 128 + out];
    } else if (idx < WCOFF) {
        int i = idx - W1OFF;
        int blk = i >> 14, r = i & 16383, out = r >> 7, k = r & 127;
        v = fc1w[((size_t)blk * 128 + k) * 128 + out];
    } else {
        int i = idx - WCOFF;
        int out = i >> 7, k = i & 127;
        v = fccw[(size_t)k * 128 + out];
    }
    g_w[idx] = __float2half_rn(v);
}

// ============ sorted-bin infrastructure ============
__global__ void zero_meta_kernel() {
    int i = blockIdx.x * 256 + threadIdx.x;
    if (i < CNTN) { g_cnt[i] = 0; g_cursor[i] = 0; }
}

__global__ void count_kernel(const int* __restrict__ ixz, const int* __restrict__ ixy,
                             const int* __restrict__ iyz) {
    int p = blockIdx.x * 256 + threadIdx.x;
    if (p >= NPTS) return;
    int b = p / TPTS;
    atomicAdd(&g_cnt[(0 * BATCH + b) * R2 + ixz[p]], 1);
    atomicAdd(&g_cnt[(1 * BATCH + b) * R2 + ixy[p]], 1);
    atomicAdd(&g_cnt[(2 * BATCH + b) * R2 + iyz[p]], 1);
}

__global__ void scan1_kernel() {
    __shared__ int smv[1024];
    int tid = threadIdx.x;
    int i = blockIdx.x * 1024 + tid;
    int v = g_cnt[i];
    smv[tid] = v;
    __syncthreads();
    for (int off = 1; off < 1024; off <<= 1) {
        int t = 0;
        if (tid >= off) t = smv[tid - off];
        __syncthreads();
        if (tid >= off) smv[tid] += t;
        __syncthreads();
    }
    g_start[i] = smv[tid] - v;
    if (tid == 1023) g_bsum[blockIdx.x] = smv[tid];
}

__global__ void scan2_kernel() {
    __shared__ int smv[128];
    int tid = threadIdx.x;
    int v = (tid < 96) ? g_bsum[tid] : 0;
    smv[tid] = v;
    __syncthreads();
    for (int off = 1; off < 128; off <<= 1) {
        int t = 0;
        if (tid >= off) t = smv[tid - off];
        __syncthreads();
        if (tid >= off) smv[tid] += t;
        __syncthreads();
    }
    if (tid < 96) g_bsum[tid] = smv[tid] - v;
}

__global__ void scan3_kernel() {
    int i = blockIdx.x * 256 + threadIdx.x;
    if (i < CNTN) g_start[i] += g_bsum[i >> 10];
}

__global__ void sortfill_kernel(const int* __restrict__ ixz, const int* __restrict__ ixy,
                                const int* __restrict__ iyz) {
    int p = blockIdx.x * 256 + threadIdx.x;
    if (p >= NPTS) return;
    int b = p / TPTS;
    int bins[3];
    bins[0] = (0 * BATCH + b) * R2 + ixz[p];
    bins[1] = (1 * BATCH + b) * R2 + ixy[p];
    bins[2] = (2 * BATCH + b) * R2 + iyz[p];
#pragma unroll
    for (int pl = 0; pl < 3; pl++) {
        int pos = atomicAdd(&g_cursor[bins[pl]], 1);
        g_sorted[g_start[bins[pl]] + pos] = p;
    }
}

__device__ __forceinline__ float4 max4(float4 a, float4 b) {
    return make_float4(fmaxf(a.x, b.x), fmaxf(a.y, b.y), fmaxf(a.z, b.z), fmaxf(a.w, b.w));
}

// pool max: warp-per-bin, float4 channels. grid = CNTN/8, block 256.
__global__ void __launch_bounds__(256)
pool_max_kernel() {
    int w = threadIdx.x >> 5, lane = threadIdx.x & 31;
    int bin = blockIdx.x * 8 + w;
    int n = g_cnt[bin];
    int st = g_start[bin];
    float4 v = make_float4(-FLT_MAX, -FLT_MAX, -FLT_MAX, -FLT_MAX);
    int i = 0;
    for (; i + 4 <= n; i += 4) {
        int p0 = g_sorted[st + i + 0];
        int p1 = g_sorted[st + i + 1];
        int p2 = g_sorted[st + i + 2];
        int p3 = g_sorted[st + i + 3];
        float4 a = *(const float4*)&g_net[(size_t)p0 * H + lane * 4];
        float4 b = *(const float4*)&g_net[(size_t)p1 * H + lane * 4];
        float4 c = *(const float4*)&g_net[(size_t)p2 * H + lane * 4];
        float4 d = *(const float4*)&g_net[(size_t)p3 * H + lane * 4];
        v = max4(v, max4(max4(a, b), max4(c, d)));
    }
    for (; i < n; i++) {
        int p = g_sorted[st + i];
        v = max4(v, *(const float4*)&g_net[(size_t)p * H + lane * 4]);
    }
    if (n > 0) *(float4*)&g_plane[(size_t)bin * H + lane * 4] = v;
}

// plane mean: warp-per-bin float4 gather + smem transpose + coalesced writes.
__global__ void __launch_bounds__(128)
mean_kernel(float* __restrict__ out) {
    __shared__ float tile[128][33];
    int pb = blockIdx.x >> 7;
    int r0 = (blockIdx.x & 127) * 32;
    int tid = threadIdx.x;
    int w = tid >> 5, lane = tid & 31;

    for (int g = 0; g < 8; g++) {
        int bb = g * 4 + w;
        int bin = pb * R2 + r0 + bb;
        int n = g_cnt[bin];
        int st = g_start[bin];
        float4 s = make_float4(0.f, 0.f, 0.f, 0.f);
        int i = 0;
        for (; i + 4 <= n; i += 4) {
            int p0 = g_sorted[st + i + 0];
            int p1 = g_sorted[st + i + 1];
            int p2 = g_sorted[st + i + 2];
            int p3 = g_sorted[st + i + 3];
            float4 a = *(const float4*)&g_c[(size_t)p0 * H + lane * 4];
            float4 b = *(const float4*)&g_c[(size_t)p1 * H + lane * 4];
            float4 c = *(const float4*)&g_c[(size_t)p2 * H + lane * 4];
            float4 d = *(const float4*)&g_c[(size_t)p3 * H + lane * 4];
            s.x += a.x + b.x + c.x + d.x;
            s.y += a.y + b.y + c.y + d.y;
            s.z += a.z + b.z + c.z + d.z;
            s.w += a.w + b.w + c.w + d.w;
        }
        for (; i < n; i++) {
            float4 a = *(const float4*)&g_c[(size_t)g_sorted[st + i] * H + lane * 4];
            s.x += a.x; s.y += a.y; s.z += a.z; s.w += a.w;
        }
        float inv = 1.0f / (float)max(n, 1);
        tile[lane * 4 + 0][bb] = s.x * inv;
        tile[lane * 4 + 1][bb] = s.y * inv;
        tile[lane * 4 + 2][bb] = s.z * inv;
        tile[lane * 4 + 3][bb] = s.w * inv;
    }
    __syncthreads();
    int rowq = tid >> 5;
    for (int it = 0; it < 32; it++) {
        int row = it * 4 + rowq;
        out[((size_t)pb * H + row) * R2 + r0 + lane] = tile[row][lane];
    }
}

extern "C" void kernel_launch(void* const* d_in, const int* in_sizes, int n_in,
                              void* d_out, int out_size) {
    const float* pts  = (const float*)d_in[0];
    const int*   ixz  = (const int*)d_in[1];
    const int*   ixy  = (const int*)d_in[2];
    const int*   iyz  = (const int*)d_in[3];
    const float* fcpw = (const float*)d_in[4];
    const float* fcpb = (const float*)d_in[5];
    const float* fc0w = (const float*)d_in[6];
    const float* fc0b = (const float*)d_in[7];
    const float* fc1w = (const float*)d_in[8];
    const float* fc1b = (const float*)d_in[9];
    const float* scw  = (const float*)d_in[10];
    const float* fccw = (const float*)d_in[11];
    const float* fccb = (const float*)d_in[12];
    float* out = (float*)d_out;

    cudaFuncSetAttribute(resnet_kernel, cudaFuncAttributeMaxDynamicSharedMemorySize, SMEM_SZ);

    prep_w_kernel<<<(WTOT + 255) / 256, 256>>>(fc0w, fc1w, scw, fccw);   // 0
    zero_meta_kernel<<<(CNTN + 255) / 256, 256>>>();                     // 1
    count_kernel<<<(NPTS + 255) / 256, 256>>>(ixz, ixy, iyz);            // 2
    // resnet block 0 at index 3 (ncu -s 5 lands here)
    resnet_kernel<<<NTILES, 512, SMEM_SZ>>>(0, pts, ixz, ixy, iyz, fcpw, fcpb,
                                            0, fc0b, fc1b, fccb);        // 3
    scan1_kernel<<<96, 1024>>>();                                        // 4
    scan2_kernel<<<1, 128>>>();                                          // 5
    scan3_kernel<<<(CNTN + 255) / 256, 256>>>();                         // 6
    sortfill_kernel<<<(NPTS + 255) / 256, 256>>>(ixz, ixy, iyz);         // 7

    for (int it = 1; it < 5; it++) {
        pool_max_kernel<<<CNTN / 8, 256>>>();
        resnet_kernel<<<NTILES, 512, SMEM_SZ>>>(1, pts, ixz, ixy, iyz, fcpw, fcpb,
                                                it, fc0b + (size_t)it * H,
                                                fc1b + (size_t)it * H, fccb);
    }
    mean_kernel<<<24 * 128, 128>>>(out);
}

// round 15
// speedup vs baseline: 1.5819x; 1.0040x over previous
#include <cuda_runtime.h>
#include <cuda_fp16.h>
#include <cfloat>
#include <cstdint>

#define BATCH 8
#define TPTS 30000
#define NPTS (BATCH*TPTS)
#define H 128
#define R2 4096
#define PTILE 128
#define NTILES (NPTS/PTILE)       // 1875
#define CNTN (3*BATCH*R2)

// transposed fp16 weight segments (element offsets): [out][k] K-major
#define W0OFF 0
#define SCOFF 163840
#define W1OFF 327680
#define WCOFF 409600
#define WTOT  425984

#define AS 264              // A row stride in fp16 (K=256 + 8 pad)
#define BSB 72              // B row stride in fp16 (K=64 chunk + 8 pad)

// smem byte layout (PTILE=128 rows)
#define SM_SBIN 0
#define SM_AH 2048
#define SM_AL (SM_AH + 128*AS*2)
#define SM_B  (SM_AL + 128*AS*2)          // 137216
#define BBUF  (128*BSB*2)                  // 18432 (fp16 B chunk)
#define SMEM_SZ (SM_B + 3*BBUF)            // 192512 -> 1 CTA/SM

typedef unsigned short u16;

__device__ __align__(16) float g_net[(size_t)NPTS*H];
__device__ __align__(16) float g_c[(size_t)NPTS*H];
__device__ __align__(16) float g_plane[(size_t)CNTN*H];
__device__ __align__(16) __half g_w[WTOT];
__device__ int g_cnt[CNTN], g_start[CNTN], g_cursor[CNTN];
__device__ int g_sorted[3*NPTS];
__device__ int g_bsum[96];

// ---------------- low-level helpers ----------------
__device__ __forceinline__ uint32_t smem_u32(const void* p) {
    uint32_t a;
    asm("{ .reg .u64 t; cvta.to.shared.u64 t, %1; cvt.u32.u64 %0, t; }" : "=r"(a) : "l"(p));
    return a;
}
__device__ __forceinline__ void cp16(uint32_t dst, const void* src) {
    asm volatile("cp.async.cg.shared.global [%0], [%1], 16;" :: "r"(dst), "l"(src));
}
#define CP_COMMIT() asm volatile("cp.async.commit_group;" ::: "memory")
#define CP_WAIT1()  asm volatile("cp.async.wait_group 1;" ::: "memory")
#define CP_WAIT0()  asm volatile("cp.async.wait_group 0;" ::: "memory")

__device__ __forceinline__ void ldmx4(uint32_t r[4], uint32_t addr) {
    asm volatile("ldmatrix.sync.aligned.m8n8.x4.shared.b16 {%0,%1,%2,%3}, [%4];"
        : "=r"(r[0]), "=r"(r[1]), "=r"(r[2]), "=r"(r[3]) : "r"(addr));
}
__device__ __forceinline__ void mma16816(float c[4], const uint32_t a[4], uint32_t b0, uint32_t b1) {
    asm volatile("mma.sync.aligned.m16n8k16.row.col.f32.f16.f16.f32 "
        "{%0,%1,%2,%3}, {%4,%5,%6,%7}, {%8,%9}, {%0,%1,%2,%3};"
        : "+f"(c[0]), "+f"(c[1]), "+f"(c[2]), "+f"(c[3])
        : "r"(a[0]), "r"(a[1]), "r"(a[2]), "r"(a[3]), "r"(b0), "r"(b1));
}

// fp16 split: v = hi + lo (~22 bits total)
__device__ __forceinline__ void dec2h(float v, u16& h, u16& l) {
    __half hb = __float2half_rn(v);
    float hf = __half2float(hb);
    __half lb = __float2half_rn(v - hf);
    h = *(u16*)&hb; l = *(u16*)&lb;
}
__device__ __forceinline__ uint32_t dec2packh(float v0, float v1, uint32_t& lop) {
    __half h0 = __float2half_rn(v0), h1 = __float2half_rn(v1);
    __half l0 = __float2half_rn(v0 - __half2float(h0));
    __half l1 = __float2half_rn(v1 - __half2float(h1));
    __half2 hp = __halves2half2(h0, h1);
    __half2 lp = __halves2half2(l0, l1);
    lop = *(uint32_t*)&lp;
    return *(uint32_t*)&hp;
}

// exact relu on split fragments: sign(v) == sign(hi)
__device__ __forceinline__ void frag_relu(uint32_t ah[4], uint32_t al[4]) {
    __half2 z = __floats2half2_rn(0.f, 0.f);
#pragma unroll
    for (int i = 0; i < 4; i++) {
        __half2 h = *(__half2*)&ah[i];
        __half2 l = *(__half2*)&al[i];
        __half2 m = __hgt2(h, z);
        h = __hmax2(h, z);
        l = __hmul2(l, m);
        ah[i] = *(uint32_t*)&h; al[i] = *(uint32_t*)&l;
    }
}

// ---------------- B chunk loader (K=64 chunk, fp16, 512 threads) ----------------
__device__ __forceinline__ void load_b(uint32_t smb, const __half* __restrict__ w,
                                       int K, int c, int buf, int tid) {
    int n = tid >> 2, qq = tid & 3;
    uint32_t d = smb + SM_B + buf * BBUF + n * (BSB * 2) + qq * 32;
    const __half* s = w + (size_t)n * K + c * 64 + qq * 16;
    cp16(d, s);
    cp16(d + 16, s + 8);
    CP_COMMIT();
}

// ---------------- one K=64 chunk of MMA work (2-pass fp16 split) ----------------
// ah/al/bb are per-thread ldmatrix base addresses (lane-resolved).
template<bool RELU>
__device__ __forceinline__ void chunk_body(uint32_t ah_p, uint32_t al_p, uint32_t bb_p,
                                           int kr0, float acc[2][4][4]) {
#pragma unroll
    for (int ks = 0; ks < 4; ks++) {
        uint32_t akoff = (uint32_t)(kr0 + ks * 16) * 2;
        uint32_t a_h[2][4], a_l[2][4];
#pragma unroll
        for (int mt = 0; mt < 2; mt++) {
            uint32_t off = akoff + mt * (16 * AS * 2);
            ldmx4(a_h[mt], ah_p + off);
            ldmx4(a_l[mt], al_p + off);
            if (RELU) frag_relu(a_h[mt], a_l[mt]);
        }
        uint32_t b0[4], b1[4];
#pragma unroll
        for (int np = 0; np < 2; np++) {
            uint32_t boff = (uint32_t)(ks * 16) * 2 + np * (16 * BSB * 2);
            uint32_t r[4];
            ldmx4(r, bb_p + boff);
            b0[2*np] = r[0]; b0[2*np+1] = r[1]; b1[2*np] = r[2]; b1[2*np+1] = r[3];
        }
#pragma unroll
        for (int mt = 0; mt < 2; mt++)
#pragma unroll
            for (int nt = 0; nt < 4; nt++) mma16816(acc[mt][nt], a_h[mt], b0[nt], b1[nt]);
#pragma unroll
        for (int mt = 0; mt < 2; mt++)
#pragma unroll
            for (int nt = 0; nt < 4; nt++) mma16816(acc[mt][nt], a_l[mt], b0[nt], b1[nt]);
    }
}

__device__ __forceinline__ void zero_acc(float acc[2][4][4]) {
#pragma unroll
    for (int i = 0; i < 2; i++)
#pragma unroll
        for (int j = 0; j < 4; j++)
#pragma unroll
            for (int k = 0; k < 4; k++) acc[i][j][k] = 0.f;
}

// chunk schedule
__device__ __forceinline__ void bsched(int c, const __half* sc, const __half* w0,
                                       const __half* w1,
                                       const __half*& w, int& K, int& cc) {
    if (c < 4)       { w = sc; K = 256; cc = c; }
    else if (c < 8)  { w = w0; K = 256; cc = c - 4; }
    else if (c < 10) { w = w1; K = 128; cc = c - 8; }
    else             { w = g_w + WCOFF; K = 128; cc = c - 10; }
}

// ---------------- fused resnet block (triple-buffered pipeline; blk==4 fuses proj) ----------------
__global__ void __launch_bounds__(512, 1)
resnet_kernel(int mode,
              const float* __restrict__ pts,
              const int* __restrict__ ixz, const int* __restrict__ ixy,
              const int* __restrict__ iyz,
              const float* __restrict__ fcpw, const float* __restrict__ fcpb,
              int blk,
              const float* __restrict__ fc0b, const float* __restrict__ fc1b,
              const float* __restrict__ bc) {
    extern __shared__ char smem[];
    uint32_t smb = smem_u32(smem);
    int tid = threadIdx.x;
    int lane = tid & 31, wid = tid >> 5;
    int m0 = (wid >> 2) * 32, n0 = (wid & 3) * 32;
    int pbase = blockIdx.x * PTILE;
    int* sbin = (int*)(smem + SM_SBIN);
    const int fuse = (blk == 4);
    const int NC = fuse ? 12 : 10;

    const __half* w0 = g_w + W0OFF + (size_t)blk * 32768;
    const __half* sc = g_w + SCOFF + (size_t)blk * 32768;
    const __half* w1 = g_w + W1OFF + (size_t)blk * 16384;

    // prologue: prime chunks 0,1 so DMA overlaps the A fill
    load_b(smb, sc, 256, 0, 0, tid);
    load_b(smb, sc, 256, 1, 1, tid);

    if (mode == 1 && tid < PTILE) {
        int gp = pbase + tid;
        int b = gp / TPTS;
        sbin[tid]             = (0 * BATCH + b) * R2 + ixz[gp];
        sbin[PTILE + tid]     = (1 * BATCH + b) * R2 + ixy[gp];
        sbin[2 * PTILE + tid] = (2 * BATCH + b) * R2 + iyz[gp];
    }
    __syncthreads();

    // ---- fill A (x) hi/lo ----
    {
        int k = tid & 255;
        int s0 = (tid >> 8) * 64;
        u16* ah = (u16*)(smem + SM_AH) + k;
        u16* al = (u16*)(smem + SM_AL) + k;
        if (mode == 0) {
            float wk0 = fcpw[k], wk1 = fcpw[256 + k], wk2 = fcpw[512 + k];
            float bk = fcpb[k];
            for (int s = s0; s < s0 + 64; s++) {
                int gp = pbase + s;
                float v = bk + pts[gp*3]*wk0 + pts[gp*3+1]*wk1 + pts[gp*3+2]*wk2;
                u16 h, l; dec2h(v, h, l);
                ah[s * AS] = h; al[s * AS] = l;
            }
        } else if (k < H) {
            for (int s = s0; s < s0 + 64; s++) {
                float v = g_net[(size_t)(pbase + s) * H + k];
                u16 h, l; dec2h(v, h, l);
                ah[s * AS] = h; al[s * AS] = l;
            }
        } else {
            int ch = k - H;
            for (int s = s0; s < s0 + 64; s++) {
                float v = g_plane[(size_t)sbin[s] * H + ch]
                        + g_plane[(size_t)sbin[PTILE + s] * H + ch]
                        + g_plane[(size_t)sbin[2 * PTILE + s] * H + ch];
                u16 h, l; dec2h(v, h, l);
                ah[s * AS] = h; al[s * AS] = l;
            }
        }
    }
    // (sync at iteration 0 orders fill vs ldmatrix)

    // per-thread ldmatrix base addresses
    uint32_t ah_p = smb + SM_AH + (uint32_t)((m0 + (lane & 15)) * AS + ((lane >> 4) << 3)) * 2;
    uint32_t al_p = smb + SM_AL + (uint32_t)((m0 + (lane & 15)) * AS + ((lane >> 4) << 3)) * 2;
    uint32_t b_rel = (uint32_t)((n0 + (lane & 15)) * BSB + ((lane >> 4) << 3)) * 2;

    float acc_sc[2][4][4], accB[2][4][4];
    zero_acc(acc_sc);
    zero_acc(accB);

    // ---- triple-buffered chunk pipeline: wait -> sync -> issue(c+2) -> body ----
    for (int c = 0; c < NC; c++) {
        if (c + 1 < NC) CP_WAIT1(); else CP_WAIT0();
        __syncthreads();

        if (c == 8) {
            // epilogue1: ns = relu(accB + b0) -> A region cols 0..127 (hi/lo)
#pragma unroll
            for (int mt = 0; mt < 2; mt++)
#pragma unroll
                for (int nt = 0; nt < 4; nt++) {
                    int row = m0 + mt * 16 + (lane >> 2);
                    int col = n0 + nt * 8 + (lane & 3) * 2;
                    float ba = fc0b[col], bb = fc0b[col + 1];
                    uint32_t lo, hi;
                    hi = dec2packh(fmaxf(accB[mt][nt][0] + ba, 0.f), fmaxf(accB[mt][nt][1] + bb, 0.f), lo);
                    *(uint32_t*)(smem + SM_AH + (row * AS + col) * 2) = hi;
                    *(uint32_t*)(smem + SM_AL + (row * AS + col) * 2) = lo;
                    hi = dec2packh(fmaxf(accB[mt][nt][2] + ba, 0.f), fmaxf(accB[mt][nt][3] + bb, 0.f), lo);
                    *(uint32_t*)(smem + SM_AH + ((row + 8) * AS + col) * 2) = hi;
                    *(uint32_t*)(smem + SM_AL + ((row + 8) * AS + col) * 2) = lo;
                }
            __syncthreads();
        }
        if (c == 10) {
            // epilogue2A (fused proj): out = acc_sc + b1 -> A region; reset accB for proj
#pragma unroll
            for (int mt = 0; mt < 2; mt++)
#pragma unroll
                for (int nt = 0; nt < 4; nt++) {
                    int row = m0 + mt * 16 + (lane >> 2);
                    int col = n0 + nt * 8 + (lane & 3) * 2;
                    float ba = fc1b[col], bb = fc1b[col + 1];
                    uint32_t lo, hi;
                    hi = dec2packh(acc_sc[mt][nt][0] + ba, acc_sc[mt][nt][1] + bb, lo);
                    *(uint32_t*)(smem + SM_AH + (row * AS + col) * 2) = hi;
                    *(uint32_t*)(smem + SM_AL + (row * AS + col) * 2) = lo;
                    hi = dec2packh(acc_sc[mt][nt][2] + ba, acc_sc[mt][nt][3] + bb, lo);
                    *(uint32_t*)(smem + SM_AH + ((row + 8) * AS + col) * 2) = hi;
                    *(uint32_t*)(smem + SM_AL + ((row + 8) * AS + col) * 2) = lo;
                }
            zero_acc(accB);
            __syncthreads();
        }

        if (c + 2 < NC) {
            const __half* nw; int nK, ncc;
            bsched(c + 2, sc, w0, w1, nw, nK, ncc);
            load_b(smb, nw, nK, ncc, (c + 2) % 3, tid);
        }

        uint32_t bb_p = smb + SM_B + (uint32_t)(c % 3) * BBUF + b_rel;
        int kr0 = ((c < 4) ? c : (c < 8) ? (c - 4) : (c < 10) ? (c - 8) : (c - 10)) * 64;

        if (c < 4 || c == 8 || c == 9)
            chunk_body<false>(ah_p, al_p, bb_p, kr0, acc_sc);
        else if (c < 8)
            chunk_body<true>(ah_p, al_p, bb_p, kr0, accB);
        else
            chunk_body<false>(ah_p, al_p, bb_p, kr0, accB);
    }

    // ---- final epilogue ----
    if (!fuse) {
#pragma unroll
        for (int mt = 0; mt < 2; mt++)
#pragma unroll
            for (int nt = 0; nt < 4; nt++) {
                int row = pbase + m0 + mt * 16 + (lane >> 2);
                int col = n0 + nt * 8 + (lane & 3) * 2;
                float ba = fc1b[col], bb = fc1b[col + 1];
                *(float2*)&g_net[(size_t)row * H + col] =
                    make_float2(acc_sc[mt][nt][0] + ba, acc_sc[mt][nt][1] + bb);
                *(float2*)&g_net[(size_t)(row + 8) * H + col] =
                    make_float2(acc_sc[mt][nt][2] + ba, acc_sc[mt][nt][3] + bb);
            }
    } else {
#pragma unroll
        for (int mt = 0; mt < 2; mt++)
#pragma unroll
            for (int nt = 0; nt < 4; nt++) {
                int row = pbase + m0 + mt * 16 + (lane >> 2);
                int col = n0 + nt * 8 + (lane & 3) * 2;
                float ba = bc[col], bb = bc[col + 1];
                *(float2*)&g_c[(size_t)row * H + col] =
                    make_float2(accB[mt][nt][0] + ba, accB[mt][nt][1] + bb);
                *(float2*)&g_c[(size_t)(row + 8) * H + col] =
                    make_float2(accB[mt][nt][2] + ba, accB[mt][nt][3] + bb);
            }
    }
}

// ---------------- weight prep: transpose + fp16 ----------------
__global__ void prep_w_kernel(const float* __restrict__ fc0w, const float* __restrict__ fc1w,
                              const float* __restrict__ scw,  const float* __restrict__ fccw) {
    int idx = blockIdx.x * 256 + threadIdx.x;
    if (idx >= WTOT) return;
    float v;
    if (idx < SCOFF) {
        int blk = idx >> 15, r = idx & 32767, out = r >> 8, k = r & 255;
        v = fc0w[((size_t)blk * 256 + k) * 128 + out];
    } else if (idx < W1OFF) {
        int i = idx - SCOFF;
        int blk = i >> 15, r = i & 32767, out = r >> 8, k = r & 255;
        v = scw[((size_t)blk * 256 + k) * 128 + out];
    } else if (idx < WCOFF) {
        int i = idx - W1OFF;
        int blk = i >> 14, r = i & 16383, out = r >> 7, k = r & 127;
        v = fc1w[((size_t)blk * 128 + k) * 128 + out];
    } else {
        int i = idx - WCOFF;
        int out = i >> 7, k = i & 127;
        v = fccw[(size_t)k * 128 + out];
    }
    g_w[idx] = __float2half_rn(v);
}

// ============ sorted-bin infrastructure ============
__global__ void zero_meta_kernel() {
    int i = blockIdx.x * 256 + threadIdx.x;
    if (i < CNTN) { g_cnt[i] = 0; g_cursor[i] = 0; }
}

__global__ void count_kernel(const int* __restrict__ ixz, const int* __restrict__ ixy,
                             const int* __restrict__ iyz) {
    int p = blockIdx.x * 256 + threadIdx.x;
    if (p >= NPTS) return;
    int b = p / TPTS;
    atomicAdd(&g_cnt[(0 * BATCH + b) * R2 + ixz[p]], 1);
    atomicAdd(&g_cnt[(1 * BATCH + b) * R2 + ixy[p]], 1);
    atomicAdd(&g_cnt[(2 * BATCH + b) * R2 + iyz[p]], 1);
}

__global__ void scan1_kernel() {
    __shared__ int smv[1024];
    int tid = threadIdx.x;
    int i = blockIdx.x * 1024 + tid;
    int v = g_cnt[i];
    smv[tid] = v;
    __syncthreads();
    for (int off = 1; off < 1024; off <<= 1) {
        int t = 0;
        if (tid >= off) t = smv[tid - off];
        __syncthreads();
        if (tid >= off) smv[tid] += t;
        __syncthreads();
    }
    g_start[i] = smv[tid] - v;
    if (tid == 1023) g_bsum[blockIdx.x] = smv[tid];
}

__global__ void scan2_kernel() {
    __shared__ int smv[128];
    int tid = threadIdx.x;
    int v = (tid < 96) ? g_bsum[tid] : 0;
    smv[tid] = v;
    __syncthreads();
    for (int off = 1; off < 128; off <<= 1) {
        int t = 0;
        if (tid >= off) t = smv[tid - off];
        __syncthreads();
        if (tid >= off) smv[tid] += t;
        __syncthreads();
    }
    if (tid < 96) g_bsum[tid] = smv[tid] - v;
}

__global__ void scan3_kernel() {
    int i = blockIdx.x * 256 + threadIdx.x;
    if (i < CNTN) g_start[i] += g_bsum[i >> 10];
}

__global__ void sortfill_kernel(const int* __restrict__ ixz, const int* __restrict__ ixy,
                                const int* __restrict__ iyz) {
    int p = blockIdx.x * 256 + threadIdx.x;
    if (p >= NPTS) return;
    int b = p / TPTS;
    int bins[3];
    bins[0] = (0 * BATCH + b) * R2 + ixz[p];
    bins[1] = (1 * BATCH + b) * R2 + ixy[p];
    bins[2] = (2 * BATCH + b) * R2 + iyz[p];
#pragma unroll
    for (int pl = 0; pl < 3; pl++) {
        int pos = atomicAdd(&g_cursor[bins[pl]], 1);
        g_sorted[g_start[bins[pl]] + pos] = p;
    }
}

__device__ __forceinline__ float4 max4(float4 a, float4 b) {
    return make_float4(fmaxf(a.x, b.x), fmaxf(a.y, b.y), fmaxf(a.z, b.z), fmaxf(a.w, b.w));
}

// pool max: warp-per-bin, float4 channels. grid = CNTN/8, block 256.
__global__ void __launch_bounds__(256)
pool_max_kernel() {
    int w = threadIdx.x >> 5, lane = threadIdx.x & 31;
    int bin = blockIdx.x * 8 + w;
    int n = g_cnt[bin];
    int st = g_start[bin];
    float4 v = make_float4(-FLT_MAX, -FLT_MAX, -FLT_MAX, -FLT_MAX);
    int i = 0;
    for (; i + 4 <= n; i += 4) {
        int p0 = g_sorted[st + i + 0];
        int p1 = g_sorted[st + i + 1];
        int p2 = g_sorted[st + i + 2];
        int p3 = g_sorted[st + i + 3];
        float4 a = *(const float4*)&g_net[(size_t)p0 * H + lane * 4];
        float4 b = *(const float4*)&g_net[(size_t)p1 * H + lane * 4];
        float4 c = *(const float4*)&g_net[(size_t)p2 * H + lane * 4];
        float4 d = *(const float4*)&g_net[(size_t)p3 * H + lane * 4];
        v = max4(v, max4(max4(a, b), max4(c, d)));
    }
    for (; i < n; i++) {
        int p = g_sorted[st + i];
        v = max4(v, *(const float4*)&g_net[(size_t)p * H + lane * 4]);
    }
    if (n > 0) *(float4*)&g_plane[(size_t)bin * H + lane * 4] = v;
}

// plane mean: warp-per-bin float4 gather + smem transpose + coalesced writes.
__global__ void __launch_bounds__(128)
mean_kernel(float* __restrict__ out) {
    __shared__ float tile[128][33];
    int pb = blockIdx.x >> 7;
    int r0 = (blockIdx.x & 127) * 32;
    int tid = threadIdx.x;
    int w = tid >> 5, lane = tid & 31;

    for (int g = 0; g < 8; g++) {
        int bb = g * 4 + w;
        int bin = pb * R2 + r0 + bb;
        int n = g_cnt[bin];
        int st = g_start[bin];
        float4 s = make_float4(0.f, 0.f, 0.f, 0.f);
        int i = 0;
        for (; i + 4 <= n; i += 4) {
            int p0 = g_sorted[st + i + 0];
            int p1 = g_sorted[st + i + 1];
            int p2 = g_sorted[st + i + 2];
            int p3 = g_sorted[st + i + 3];
            float4 a = *(const float4*)&g_c[(size_t)p0 * H + lane * 4];
            float4 b = *(const float4*)&g_c[(size_t)p1 * H + lane * 4];
            float4 c = *(const float4*)&g_c[(size_t)p2 * H + lane * 4];
            float4 d = *(const float4*)&g_c[(size_t)p3 * H + lane * 4];
            s.x += a.x + b.x + c.x + d.x;
            s.y += a.y + b.y + c.y + d.y;
            s.z += a.z + b.z + c.z + d.z;
            s.w += a.w + b.w + c.w + d.w;
        }
        for (; i < n; i++) {
            float4 a = *(const float4*)&g_c[(size_t)g_sorted[st + i] * H + lane * 4];
            s.x += a.x; s.y += a.y; s.z += a.z; s.w += a.w;
        }
        float inv = 1.0f / (float)max(n, 1);
        tile[lane * 4 + 0][bb] = s.x * inv;
        tile[lane * 4 + 1][bb] = s.y * inv;
        tile[lane * 4 + 2][bb] = s.z * inv;
        tile[lane * 4 + 3][bb] = s.w * inv;
    }
    __syncthreads();
    int rowq = tid >> 5;
    for (int it = 0; it < 32; it++) {
        int row = it * 4 + rowq;
        out[((size_t)pb * H + row) * R2 + r0 + lane] = tile[row][lane];
    }
}

extern "C" void kernel_launch(void* const* d_in, const int* in_sizes, int n_in,
                              void* d_out, int out_size) {
    const float* pts  = (const float*)d_in[0];
    const int*   ixz  = (const int*)d_in[1];
    const int*   ixy  = (const int*)d_in[2];
    const int*   iyz  = (const int*)d_in[3];
    const float* fcpw = (const float*)d_in[4];
    const float* fcpb = (const float*)d_in[5];
    const float* fc0w = (const float*)d_in[6];
    const float* fc0b = (const float*)d_in[7];
    const float* fc1w = (const float*)d_in[8];
    const float* fc1b = (const float*)d_in[9];
    const float* scw  = (const float*)d_in[10];
    const float* fccw = (const float*)d_in[11];
    const float* fccb = (const float*)d_in[12];
    float* out = (float*)d_out;

    cudaFuncSetAttribute(resnet_kernel, cudaFuncAttributeMaxDynamicSharedMemorySize, SMEM_SZ);

    prep_w_kernel<<<(WTOT + 255) / 256, 256>>>(fc0w, fc1w, scw, fccw);   // 0
    zero_meta_kernel<<<(CNTN + 255) / 256, 256>>>();                     // 1
    count_kernel<<<(NPTS + 255) / 256, 256>>>(ixz, ixy, iyz);            // 2
    // resnet block 0 at index 3 (ncu -s 5 lands here)
    resnet_kernel<<<NTILES, 512, SMEM_SZ>>>(0, pts, ixz, ixy, iyz, fcpw, fcpb,
                                            0, fc0b, fc1b, fccb);        // 3
    scan1_kernel<<<96, 1024>>>();                                        // 4
    scan2_kernel<<<1, 128>>>();                                          // 5
    scan3_kernel<<<(CNTN + 255) / 256, 256>>>();                         // 6
    sortfill_kernel<<<(NPTS + 255) / 256, 256>>>(ixz, ixy, iyz);         // 7

    for (int it = 1; it < 5; it++) {
        pool_max_kernel<<<CNTN / 8, 256>>>();
        resnet_kernel<<<NTILES, 512, SMEM_SZ>>>(1, pts, ixz, ixy, iyz, fcpw, fcpb,
                                                it, fc0b + (size_t)it * H,
                                                fc1b + (size_t)it * H, fccb);
    }
    mean_kernel<<<24 * 128, 128>>>(out);
}

// round 16
// speedup vs baseline: 1.6071x; 1.0160x over previous
#include <cuda_runtime.h>
#include <cuda_fp16.h>
#include <cfloat>
#include <cstdint>

#define BATCH 8
#define TPTS 30000
#define NPTS (BATCH*TPTS)
#define H 128
#define R2 4096
#define PTILE 64
#define NTILES (NPTS/PTILE)       // 3750
#define CNTN (3*BATCH*R2)

// transposed fp16 weight segments (element offsets): [out][k] K-major
#define W0OFF 0
#define SCOFF 163840
#define W1OFF 327680
#define WCOFF 409600
#define WTOT  425984

#define AS 264              // A row stride in fp16 (K=256 + 8 pad)
#define BSB 72              // B row stride in fp16 (K=64 chunk + 8 pad)

// smem byte layout (PTILE=64 rows)
#define SM_SBIN 0
#define SM_AH 2048
#define SM_AL (SM_AH + 64*AS*2)           // +33792
#define SM_B  (SM_AL + 64*AS*2)           // 69632
#define BBUF  (128*BSB*2)                  // 18432 (fp16 B chunk)
#define SMEM_SZ (SM_B + 2*BBUF)            // 106496 -> 2 CTAs/SM

typedef unsigned short u16;

__device__ __align__(16) float g_net[(size_t)NPTS*H];
__device__ __align__(16) float g_c[(size_t)NPTS*H];
__device__ __align__(16) float g_plane[(size_t)CNTN*H];
__device__ __align__(16) __half g_w[WTOT];
__device__ int g_cnt[CNTN], g_start[CNTN], g_cursor[CNTN];
__device__ int g_sorted[3*NPTS];
__device__ int g_bsum[96];

// ---------------- low-level helpers ----------------
__device__ __forceinline__ uint32_t smem_u32(const void* p) {
    uint32_t a;
    asm("{ .reg .u64 t; cvta.to.shared.u64 t, %1; cvt.u32.u64 %0, t; }" : "=r"(a) : "l"(p));
    return a;
}
__device__ __forceinline__ void cp16(uint32_t dst, const void* src) {
    asm volatile("cp.async.cg.shared.global [%0], [%1], 16;" :: "r"(dst), "l"(src));
}
#define CP_COMMIT() asm volatile("cp.async.commit_group;" ::: "memory")
#define CP_WAIT1()  asm volatile("cp.async.wait_group 1;" ::: "memory")
#define CP_WAIT0()  asm volatile("cp.async.wait_group 0;" ::: "memory")

__device__ __forceinline__ void ldmx4(uint32_t r[4], uint32_t addr) {
    asm volatile("ldmatrix.sync.aligned.m8n8.x4.shared.b16 {%0,%1,%2,%3}, [%4];"
        : "=r"(r[0]), "=r"(r[1]), "=r"(r[2]), "=r"(r[3]) : "r"(addr));
}
__device__ __forceinline__ void mma16816(float c[4], const uint32_t a[4], uint32_t b0, uint32_t b1) {
    asm volatile("mma.sync.aligned.m16n8k16.row.col.f32.f16.f16.f32 "
        "{%0,%1,%2,%3}, {%4,%5,%6,%7}, {%8,%9}, {%0,%1,%2,%3};"
        : "+f"(c[0]), "+f"(c[1]), "+f"(c[2]), "+f"(c[3])
        : "r"(a[0]), "r"(a[1]), "r"(a[2]), "r"(a[3]), "r"(b0), "r"(b1));
}

// fp16 split: v = hi + lo (~22 bits total)
__device__ __forceinline__ void dec2h(float v, u16& h, u16& l) {
    __half hb = __float2half_rn(v);
    float hf = __half2float(hb);
    __half lb = __float2half_rn(v - hf);
    h = *(u16*)&hb; l = *(u16*)&lb;
}
__device__ __forceinline__ uint32_t dec2packh(float v0, float v1, uint32_t& lop) {
    __half h0 = __float2half_rn(v0), h1 = __float2half_rn(v1);
    __half l0 = __float2half_rn(v0 - __half2float(h0));
    __half l1 = __float2half_rn(v1 - __half2float(h1));
    __half2 hp = __halves2half2(h0, h1);
    __half2 lp = __halves2half2(l0, l1);
    lop = *(uint32_t*)&lp;
    return *(uint32_t*)&hp;
}

// exact relu on split fragments: sign(v) == sign(hi)
__device__ __forceinline__ void frag_relu(uint32_t ah[4], uint32_t al[4]) {
    __half2 z = __floats2half2_rn(0.f, 0.f);
#pragma unroll
    for (int i = 0; i < 4; i++) {
        __half2 h = *(__half2*)&ah[i];
        __half2 l = *(__half2*)&al[i];
        __half2 m = __hgt2(h, z);
        h = __hmax2(h, z);
        l = __hmul2(l, m);
        ah[i] = *(uint32_t*)&h; al[i] = *(uint32_t*)&l;
    }
}

// ---------------- B chunk loader (K=64 chunk, fp16, 256 threads) ----------------
__device__ __forceinline__ void load_b(uint32_t smb, const __half* __restrict__ w,
                                       int K, int c, int buf, int tid) {
    int n = tid >> 1, half = tid & 1;
    uint32_t d = smb + SM_B + buf * BBUF + n * (BSB * 2) + half * 64;
    const __half* s = w + (size_t)n * K + c * 64 + half * 32;
    cp16(d, s);       cp16(d + 16, s + 8);
    cp16(d + 32, s + 16); cp16(d + 48, s + 24);
    CP_COMMIT();
}

// ---------------- one K=64 chunk of MMA work (2-pass fp16 split) ----------------
template<bool RELU>
__device__ __forceinline__ void chunk_body(uint32_t ah_p, uint32_t al_p, uint32_t bb_p,
                                           int kr0, float acc[2][4][4]) {
#pragma unroll
    for (int ks = 0; ks < 4; ks++) {
        uint32_t akoff = (uint32_t)(kr0 + ks * 16) * 2;
        uint32_t a_h[2][4], a_l[2][4];
#pragma unroll
        for (int mt = 0; mt < 2; mt++) {
            uint32_t off = akoff + mt * (16 * AS * 2);
            ldmx4(a_h[mt], ah_p + off);
            ldmx4(a_l[mt], al_p + off);
            if (RELU) frag_relu(a_h[mt], a_l[mt]);
        }
        uint32_t b0[4], b1[4];
#pragma unroll
        for (int np = 0; np < 2; np++) {
            uint32_t boff = (uint32_t)(ks * 16) * 2 + np * (16 * BSB * 2);
            uint32_t r[4];
            ldmx4(r, bb_p + boff);
            b0[2*np] = r[0]; b0[2*np+1] = r[1]; b1[2*np] = r[2]; b1[2*np+1] = r[3];
        }
#pragma unroll
        for (int mt = 0; mt < 2; mt++)
#pragma unroll
            for (int nt = 0; nt < 4; nt++) mma16816(acc[mt][nt], a_h[mt], b0[nt], b1[nt]);
#pragma unroll
        for (int mt = 0; mt < 2; mt++)
#pragma unroll
            for (int nt = 0; nt < 4; nt++) mma16816(acc[mt][nt], a_l[mt], b0[nt], b1[nt]);
    }
}

__device__ __forceinline__ void zero_acc(float acc[2][4][4]) {
#pragma unroll
    for (int i = 0; i < 2; i++)
#pragma unroll
        for (int j = 0; j < 4; j++)
#pragma unroll
            for (int k = 0; k < 4; k++) acc[i][j][k] = 0.f;
}

// chunk schedule
__device__ __forceinline__ void bsched(int c, const __half* sc, const __half* w0,
                                       const __half* w1,
                                       const __half*& w, int& K, int& cc) {
    if (c < 4)       { w = sc; K = 256; cc = c; }
    else if (c < 8)  { w = w0; K = 256; cc = c - 4; }
    else if (c < 10) { w = w1; K = 128; cc = c - 8; }
    else             { w = g_w + WCOFF; K = 128; cc = c - 10; }
}

// ---------------- fused resnet block (PTILE=64, 2 CTAs/SM; blk==4 fuses proj) ----------------
__global__ void __launch_bounds__(256, 2)
resnet_kernel(int mode,
              const float* __restrict__ pts,
              const int* __restrict__ ixz, const int* __restrict__ ixy,
              const int* __restrict__ iyz,
              const float* __restrict__ fcpw, const float* __restrict__ fcpb,
              int blk,
              const float* __restrict__ fc0b, const float* __restrict__ fc1b,
              const float* __restrict__ bc) {
    extern __shared__ char smem[];
    uint32_t smb = smem_u32(smem);
    int tid = threadIdx.x;
    int lane = tid & 31, wid = tid >> 5;
    int m0 = (wid >> 2) * 32, n0 = (wid & 3) * 32;
    int pbase = blockIdx.x * PTILE;
    int* sbin = (int*)(smem + SM_SBIN);
    const int fuse = (blk == 4);
    const int NC = fuse ? 12 : 10;

    const __half* w0 = g_w + W0OFF + (size_t)blk * 32768;
    const __half* sc = g_w + SCOFF + (size_t)blk * 32768;
    const __half* w1 = g_w + W1OFF + (size_t)blk * 16384;

    // prime chunk 0 so DMA overlaps the A fill
    load_b(smb, sc, 256, 0, 0, tid);

    if (mode == 1 && tid < 192) {
        int pl = tid >> 6, s = tid & 63;
        int gp = pbase + s;
        int b = gp / TPTS;
        const int* ix = (pl == 0) ? ixz : (pl == 1) ? ixy : iyz;
        sbin[pl * PTILE + s] = (pl * BATCH + b) * R2 + ix[gp];
    }
    __syncthreads();

    // ---- fill A (x) hi/lo: thread k handles all 64 points ----
    {
        int k = tid;
        u16* ah = (u16*)(smem + SM_AH) + k;
        u16* al = (u16*)(smem + SM_AL) + k;
        if (mode == 0) {
            float wk0 = fcpw[k], wk1 = fcpw[256 + k], wk2 = fcpw[512 + k];
            float bk = fcpb[k];
            for (int s = 0; s < PTILE; s++) {
                int gp = pbase + s;
                float v = bk + pts[gp*3]*wk0 + pts[gp*3+1]*wk1 + pts[gp*3+2]*wk2;
                u16 h, l; dec2h(v, h, l);
                ah[s * AS] = h; al[s * AS] = l;
            }
        } else if (k < H) {
            for (int s = 0; s < PTILE; s++) {
                float v = g_net[(size_t)(pbase + s) * H + k];
                u16 h, l; dec2h(v, h, l);
                ah[s * AS] = h; al[s * AS] = l;
            }
        } else {
            int ch = k - H;
            for (int s = 0; s < PTILE; s++) {
                float v = g_plane[(size_t)sbin[s] * H + ch]
                        + g_plane[(size_t)sbin[PTILE + s] * H + ch]
                        + g_plane[(size_t)sbin[2 * PTILE + s] * H + ch];
                u16 h, l; dec2h(v, h, l);
                ah[s * AS] = h; al[s * AS] = l;
            }
        }
    }
    // (sync at iteration 0 orders fill vs ldmatrix)

    // per-thread ldmatrix base addresses
    uint32_t ah_p = smb + SM_AH + (uint32_t)((m0 + (lane & 15)) * AS + ((lane >> 4) << 3)) * 2;
    uint32_t al_p = smb + SM_AL + (uint32_t)((m0 + (lane & 15)) * AS + ((lane >> 4) << 3)) * 2;
    uint32_t b_rel = (uint32_t)((n0 + (lane & 15)) * BSB + ((lane >> 4) << 3)) * 2;

    float acc_sc[2][4][4], accB[2][4][4];
    zero_acc(acc_sc);
    zero_acc(accB);

    // ---- double-buffered chunk pipeline ----
    for (int c = 0; c < NC; c++) {
        if (c + 1 < NC) {
            const __half* nw; int nK, ncc;
            bsched(c + 1, sc, w0, w1, nw, nK, ncc);
            load_b(smb, nw, nK, ncc, (c + 1) & 1, tid);
            CP_WAIT1();
        } else CP_WAIT0();
        __syncthreads();

        if (c == 8) {
            // epilogue1: ns = relu(accB + b0) -> A region cols 0..127 (hi/lo)
#pragma unroll
            for (int mt = 0; mt < 2; mt++)
#pragma unroll
                for (int nt = 0; nt < 4; nt++) {
                    int row = m0 + mt * 16 + (lane >> 2);
                    int col = n0 + nt * 8 + (lane & 3) * 2;
                    float ba = fc0b[col], bb = fc0b[col + 1];
                    uint32_t lo, hi;
                    hi = dec2packh(fmaxf(accB[mt][nt][0] + ba, 0.f), fmaxf(accB[mt][nt][1] + bb, 0.f), lo);
                    *(uint32_t*)(smem + SM_AH + (row * AS + col) * 2) = hi;
                    *(uint32_t*)(smem + SM_AL + (row * AS + col) * 2) = lo;
                    hi = dec2packh(fmaxf(accB[mt][nt][2] + ba, 0.f), fmaxf(accB[mt][nt][3] + bb, 0.f), lo);
                    *(uint32_t*)(smem + SM_AH + ((row + 8) * AS + col) * 2) = hi;
                    *(uint32_t*)(smem + SM_AL + ((row + 8) * AS + col) * 2) = lo;
                }
            __syncthreads();
        }
        if (c == 10) {
            // epilogue2A (fused proj): out = acc_sc + b1 -> A region; reset accB
#pragma unroll
            for (int mt = 0; mt < 2; mt++)
#pragma unroll
                for (int nt = 0; nt < 4; nt++) {
                    int row = m0 + mt * 16 + (lane >> 2);
                    int col = n0 + nt * 8 + (lane & 3) * 2;
                    float ba = fc1b[col], bb = fc1b[col + 1];
                    uint32_t lo, hi;
                    hi = dec2packh(acc_sc[mt][nt][0] + ba, acc_sc[mt][nt][1] + bb, lo);
                    *(uint32_t*)(smem + SM_AH + (row * AS + col) * 2) = hi;
                    *(uint32_t*)(smem + SM_AL + (row * AS + col) * 2) = lo;
                    hi = dec2packh(acc_sc[mt][nt][2] + ba, acc_sc[mt][nt][3] + bb, lo);
                    *(uint32_t*)(smem + SM_AH + ((row + 8) * AS + col) * 2) = hi;
                    *(uint32_t*)(smem + SM_AL + ((row + 8) * AS + col) * 2) = lo;
                }
            zero_acc(accB);
            __syncthreads();
        }

        uint32_t bb_p = smb + SM_B + (uint32_t)(c & 1) * BBUF + b_rel;
        int kr0 = ((c < 4) ? c : (c < 8) ? (c - 4) : (c < 10) ? (c - 8) : (c - 10)) * 64;

        if (c < 4 || c == 8 || c == 9)
            chunk_body<false>(ah_p, al_p, bb_p, kr0, acc_sc);
        else if (c < 8)
            chunk_body<true>(ah_p, al_p, bb_p, kr0, accB);
        else
            chunk_body<false>(ah_p, al_p, bb_p, kr0, accB);

        __syncthreads();
    }

    // ---- final epilogue ----
    if (!fuse) {
#pragma unroll
        for (int mt = 0; mt < 2; mt++)
#pragma unroll
            for (int nt = 0; nt < 4; nt++) {
                int row = pbase + m0 + mt * 16 + (lane >> 2);
                int col = n0 + nt * 8 + (lane & 3) * 2;
                float ba = fc1b[col], bb = fc1b[col + 1];
                *(float2*)&g_net[(size_t)row * H + col] =
                    make_float2(acc_sc[mt][nt][0] + ba, acc_sc[mt][nt][1] + bb);
                *(float2*)&g_net[(size_t)(row + 8) * H + col] =
                    make_float2(acc_sc[mt][nt][2] + ba, acc_sc[mt][nt][3] + bb);
            }
    } else {
#pragma unroll
        for (int mt = 0; mt < 2; mt++)
#pragma unroll
            for (int nt = 0; nt < 4; nt++) {
                int row = pbase + m0 + mt * 16 + (lane >> 2);
                int col = n0 + nt * 8 + (lane & 3) * 2;
                float ba = bc[col], bb = bc[col + 1];
                *(float2*)&g_c[(size_t)row * H + col] =
                    make_float2(accB[mt][nt][0] + ba, accB[mt][nt][1] + bb);
                *(float2*)&g_c[(size_t)(row + 8) * H + col] =
                    make_float2(accB[mt][nt][2] + ba, accB[mt][nt][3] + bb);
            }
    }
}

// ---------------- weight prep: transpose + fp16 ----------------
__global__ void prep_w_kernel(const float* __restrict__ fc0w, const float* __restrict__ fc1w,
                              const float* __restrict__ scw,  const float* __restrict__ fccw) {
    int idx = blockIdx.x * 256 + threadIdx.x;
    if (idx >= WTOT) return;
    float v;
    if (idx < SCOFF) {
        int blk = idx >> 15, r = idx & 32767, out = r >> 8, k = r & 255;
        v = fc0w[((size_t)blk * 256 + k) * 128 + out];
    } else if (idx < W1OFF) {
        int i = idx - SCOFF;
        int blk = i >> 15, r = i & 32767, out = r >> 8, k = r & 255;
        v = scw[((size_t)blk * 256 + k) * 128 + out];
    } else if (idx < WCOFF) {
        int i = idx - W1OFF;
        int blk = i >> 14, r = i & 16383, out = r >> 7, k = r & 127;
        v = fc1w[((size_t)blk * 128 + k) * 128 + out];
    } else {
        int i = idx - WCOFF;
        int out = i >> 7, k = i & 127;
        v = fccw[(size_t)k * 128 + out];
    }
    g_w[idx] = __float2half_rn(v);
}

// ============ sorted-bin infrastructure ============
__global__ void zero_meta_kernel() {
    int i = blockIdx.x * 256 + threadIdx.x;
    if (i < CNTN) { g_cnt[i] = 0; g_cursor[i] = 0; }
}

__global__ void count_kernel(const int* __restrict__ ixz, const int* __restrict__ ixy,
                             const int* __restrict__ iyz) {
    int p = blockIdx.x * 256 + threadIdx.x;
    if (p >= NPTS) return;
    int b = p / TPTS;
    atomicAdd(&g_cnt[(0 * BATCH + b) * R2 + ixz[p]], 1);
    atomicAdd(&g_cnt[(1 * BATCH + b) * R2 + ixy[p]], 1);
    atomicAdd(&g_cnt[(2 * BATCH + b) * R2 + iyz[p]], 1);
}

__global__ void scan1_kernel() {
    __shared__ int smv[1024];
    int tid = threadIdx.x;
    int i = blockIdx.x * 1024 + tid;
    int v = g_cnt[i];
    smv[tid] = v;
    __syncthreads();
    for (int off = 1; off < 1024; off <<= 1) {
        int t = 0;
        if (tid >= off) t = smv[tid - off];
        __syncthreads();
        if (tid >= off) smv[tid] += t;
        __syncthreads();
    }
    g_start[i] = smv[tid] - v;
    if (tid == 1023) g_bsum[blockIdx.x] = smv[tid];
}

__global__ void scan2_kernel() {
    __shared__ int smv[128];
    int tid = threadIdx.x;
    int v = (tid < 96) ? g_bsum[tid] : 0;
    smv[tid] = v;
    __syncthreads();
    for (int off = 1; off < 128; off <<= 1) {
        int t = 0;
        if (tid >= off) t = smv[tid - off];
        __syncthreads();
        if (tid >= off) smv[tid] += t;
        __syncthreads();
    }
    if (tid < 96) g_bsum[tid] = smv[tid] - v;
}

__global__ void scan3_kernel() {
    int i = blockIdx.x * 256 + threadIdx.x;
    if (i < CNTN) g_start[i] += g_bsum[i >> 10];
}

__global__ void sortfill_kernel(const int* __restrict__ ixz, const int* __restrict__ ixy,
                                const int* __restrict__ iyz) {
    int p = blockIdx.x * 256 + threadIdx.x;
    if (p >= NPTS) return;
    int b = p / TPTS;
    int bins[3];
    bins[0] = (0 * BATCH + b) * R2 + ixz[p];
    bins[1] = (1 * BATCH + b) * R2 + ixy[p];
    bins[2] = (2 * BATCH + b) * R2 + iyz[p];
#pragma unroll
    for (int pl = 0; pl < 3; pl++) {
        int pos = atomicAdd(&g_cursor[bins[pl]], 1);
        g_sorted[g_start[bins[pl]] + pos] = p;
    }
}

__device__ __forceinline__ float4 max4(float4 a, float4 b) {
    return make_float4(fmaxf(a.x, b.x), fmaxf(a.y, b.y), fmaxf(a.z, b.z), fmaxf(a.w, b.w));
}

// pool max: warp-per-bin, MLP-8 batched float4 gathers. grid = CNTN/8, block 256.
__global__ void __launch_bounds__(256)
pool_max_kernel() {
    int w = threadIdx.x >> 5, lane = threadIdx.x & 31;
    int bin = blockIdx.x * 8 + w;
    int n = g_cnt[bin];
    if (n == 0) return;
    int st = g_start[bin];
    float4 v = make_float4(-FLT_MAX, -FLT_MAX, -FLT_MAX, -FLT_MAX);
    for (int i = 0; i < n; i += 8) {
        int m = n - i;
        int p0 = g_sorted[st + i];
        int p[8];
#pragma unroll
        for (int j = 0; j < 8; j++) p[j] = (j < m) ? g_sorted[st + i + j] : p0;
        float4 x[8];
#pragma unroll
        for (int j = 0; j < 8; j++) x[j] = *(const float4*)&g_net[(size_t)p[j] * H + lane * 4];
#pragma unroll
        for (int j = 0; j < 8; j++) if (j < m) v = max4(v, x[j]);
    }
    *(float4*)&g_plane[(size_t)bin * H + lane * 4] = v;
}

// plane mean: warp-per-bin MLP-8 float4 gather + smem transpose + coalesced writes.
__global__ void __launch_bounds__(128)
mean_kernel(float* __restrict__ out) {
    __shared__ float tile[128][33];
    int pb = blockIdx.x >> 7;
    int r0 = (blockIdx.x & 127) * 32;
    int tid = threadIdx.x;
    int w = tid >> 5, lane = tid & 31;

    for (int g = 0; g < 8; g++) {
        int bb = g * 4 + w;
        int bin = pb * R2 + r0 + bb;
        int n = g_cnt[bin];
        int st = g_start[bin];
        float4 s = make_float4(0.f, 0.f, 0.f, 0.f);
        for (int i = 0; i < n; i += 8) {
            int m = n - i;
            int p0 = g_sorted[st + i];
            int p[8];
#pragma unroll
            for (int j = 0; j < 8; j++) p[j] = (j < m) ? g_sorted[st + i + j] : p0;
            float4 x[8];
#pragma unroll
            for (int j = 0; j < 8; j++) x[j] = *(const float4*)&g_c[(size_t)p[j] * H + lane * 4];
#pragma unroll
            for (int j = 0; j < 8; j++)
                if (j < m) { s.x += x[j].x; s.y += x[j].y; s.z += x[j].z; s.w += x[j].w; }
        }
        float inv = 1.0f / (float)max(n, 1);
        tile[lane * 4 + 0][bb] = s.x * inv;
        tile[lane * 4 + 1][bb] = s.y * inv;
        tile[lane * 4 + 2][bb] = s.z * inv;
        tile[lane * 4 + 3][bb] = s.w * inv;
    }
    __syncthreads();
    int rowq = tid >> 5;
    for (int it = 0; it < 32; it++) {
        int row = it * 4 + rowq;
        out[((size_t)pb * H + row) * R2 + r0 + lane] = tile[row][lane];
    }
}

extern "C" void kernel_launch(void* const* d_in, const int* in_sizes, int n_in,
                              void* d_out, int out_size) {
    const float* pts  = (const float*)d_in[0];
    const int*   ixz  = (const int*)d_in[1];
    const int*   ixy  = (const int*)d_in[2];
    const int*   iyz  = (const int*)d_in[3];
    const float* fcpw = (const float*)d_in[4];
    const float* fcpb = (const float*)d_in[5];
    const float* fc0w = (const float*)d_in[6];
    const float* fc0b = (const float*)d_in[7];
    const float* fc1w = (const float*)d_in[8];
    const float* fc1b = (const float*)d_in[9];
    const float* scw  = (const float*)d_in[10];
    const float* fccw = (const float*)d_in[11];
    const float* fccb = (const float*)d_in[12];
    float* out = (float*)d_out;

    cudaFuncSetAttribute(resnet_kernel, cudaFuncAttributeMaxDynamicSharedMemorySize, SMEM_SZ);

    prep_w_kernel<<<(WTOT + 255) / 256, 256>>>(fc0w, fc1w, scw, fccw);   // 0
    zero_meta_kernel<<<(CNTN + 255) / 256, 256>>>();                     // 1
    count_kernel<<<(NPTS + 255) / 256, 256>>>(ixz, ixy, iyz);            // 2
    // resnet block 0 at index 3 (ncu -s 5 lands here)
    resnet_kernel<<<NTILES, 256, SMEM_SZ>>>(0, pts, ixz, ixy, iyz, fcpw, fcpb,
                                            0, fc0b, fc1b, fccb);        // 3
    scan1_kernel<<<96, 1024>>>();                                        // 4
    scan2_kernel<<<1, 128>>>();                                          // 5
    scan3_kernel<<<(CNTN + 255) / 256, 256>>>();                         // 6
    sortfill_kernel<<<(NPTS + 255) / 256, 256>>>(ixz, ixy, iyz);         // 7

    for (int it = 1; it < 5; it++) {
        pool_max_kernel<<<CNTN / 8, 256>>>();
        resnet_kernel<<<NTILES, 256, SMEM_SZ>>>(1, pts, ixz, ixy, iyz, fcpw, fcpb,
                                                it, fc0b + (size_t)it * H,
                                                fc1b + (size_t)it * H, fccb);
    }
    mean_kernel<<<24 * 128, 128>>>(out);
}

// round 17
// speedup vs baseline: 1.7115x; 1.0649x over previous
#include <cuda_runtime.h>
#include <cuda_fp16.h>
#include <cfloat>
#include <cstdint>

#define BATCH 8
#define TPTS 30000
#define NPTS (BATCH*TPTS)
#define H 128
#define R2 4096
#define PTILE 64
#define NTILES (NPTS/PTILE)       // 3750
#define CNTN (3*BATCH*R2)

// transposed fp16 weight segments (element offsets): [out][k] K-major
#define W0OFF 0
#define SCOFF 163840
#define W1OFF 327680
#define WCOFF 409600
#define WTOT  425984

#define AS 264              // A row stride in fp16 (K=256 + 8 pad)
#define BSB 72              // B row stride in fp16 (K=64 chunk + 8 pad)

// smem byte layout (PTILE=64 rows)
#define SM_SBIN 0
#define SM_AH 2048
#define SM_AL (SM_AH + 64*AS*2)           // +33792
#define SM_B  (SM_AL + 64*AS*2)           // 69632
#define BBUF  (128*BSB*2)                  // 18432 (fp16 B chunk)
#define SMEM_SZ (SM_B + 2*BBUF)            // 106496 -> 2 CTAs/SM

typedef unsigned short u16;

__device__ __align__(16) float g_net[(size_t)NPTS*H];
__device__ __align__(16) float g_c[(size_t)NPTS*H];
__device__ __align__(16) float g_plane[(size_t)CNTN*H];
__device__ __align__(16) __half g_w[WTOT];
__device__ int g_cnt[CNTN], g_start[CNTN], g_cursor[CNTN];
__device__ int g_sorted[3*NPTS];
__device__ int g_bsum[96];

// ---------------- low-level helpers ----------------
__device__ __forceinline__ uint32_t smem_u32(const void* p) {
    uint32_t a;
    asm("{ .reg .u64 t; cvta.to.shared.u64 t, %1; cvt.u32.u64 %0, t; }" : "=r"(a) : "l"(p));
    return a;
}
__device__ __forceinline__ void cp16(uint32_t dst, const void* src) {
    asm volatile("cp.async.cg.shared.global [%0], [%1], 16;" :: "r"(dst), "l"(src));
}
#define CP_COMMIT() asm volatile("cp.async.commit_group;" ::: "memory")
#define CP_WAIT1()  asm volatile("cp.async.wait_group 1;" ::: "memory")
#define CP_WAIT0()  asm volatile("cp.async.wait_group 0;" ::: "memory")

__device__ __forceinline__ void ldmx4(uint32_t r[4], uint32_t addr) {
    asm volatile("ldmatrix.sync.aligned.m8n8.x4.shared.b16 {%0,%1,%2,%3}, [%4];"
        : "=r"(r[0]), "=r"(r[1]), "=r"(r[2]), "=r"(r[3]) : "r"(addr));
}
__device__ __forceinline__ void mma16816(float c[4], const uint32_t a[4], uint32_t b0, uint32_t b1) {
    asm volatile("mma.sync.aligned.m16n8k16.row.col.f32.f16.f16.f32 "
        "{%0,%1,%2,%3}, {%4,%5,%6,%7}, {%8,%9}, {%0,%1,%2,%3};"
        : "+f"(c[0]), "+f"(c[1]), "+f"(c[2]), "+f"(c[3])
        : "r"(a[0]), "r"(a[1]), "r"(a[2]), "r"(a[3]), "r"(b0), "r"(b1));
}

// fp16 split: v = hi + lo (~22 bits total)
__device__ __forceinline__ void dec2h(float v, u16& h, u16& l) {
    __half hb = __float2half_rn(v);
    float hf = __half2float(hb);
    __half lb = __float2half_rn(v - hf);
    h = *(u16*)&hb; l = *(u16*)&lb;
}
__device__ __forceinline__ uint32_t dec2packh(float v0, float v1, uint32_t& lop) {
    __half h0 = __float2half_rn(v0), h1 = __float2half_rn(v1);
    __half l0 = __float2half_rn(v0 - __half2float(h0));
    __half l1 = __float2half_rn(v1 - __half2float(h1));
    __half2 hp = __halves2half2(h0, h1);
    __half2 lp = __halves2half2(l0, l1);
    lop = *(uint32_t*)&lp;
    return *(uint32_t*)&hp;
}

// exact relu on split fragments: sign(v) == sign(hi)
__device__ __forceinline__ void frag_relu(uint32_t ah[4], uint32_t al[4]) {
    __half2 z = __floats2half2_rn(0.f, 0.f);
#pragma unroll
    for (int i = 0; i < 4; i++) {
        __half2 h = *(__half2*)&ah[i];
        __half2 l = *(__half2*)&al[i];
        __half2 m = __hgt2(h, z);
        h = __hmax2(h, z);
        l = __hmul2(l, m);
        ah[i] = *(uint32_t*)&h; al[i] = *(uint32_t*)&l;
    }
}

// decompose float4 and store as two ushort4 (hi, lo)
__device__ __forceinline__ void dec4_store(char* smem, int off16, float4 v) {
    u16 h0, l0, h1, l1, h2, l2, h3, l3;
    dec2h(v.x, h0, l0); dec2h(v.y, h1, l1);
    dec2h(v.z, h2, l2); dec2h(v.w, h3, l3);
    *(ushort4*)(smem + SM_AH + off16 * 2) = make_ushort4(h0, h1, h2, h3);
    *(ushort4*)(smem + SM_AL + off16 * 2) = make_ushort4(l0, l1, l2, l3);
}

// ---------------- B chunk loader (K=64 chunk, fp16, 256 threads) ----------------
__device__ __forceinline__ void load_b(uint32_t smb, const __half* __restrict__ w,
                                       int K, int c, int buf, int tid) {
    int n = tid >> 1, half = tid & 1;
    uint32_t d = smb + SM_B + buf * BBUF + n * (BSB * 2) + half * 64;
    const __half* s = w + (size_t)n * K + c * 64 + half * 32;
    cp16(d, s);       cp16(d + 16, s + 8);
    cp16(d + 32, s + 16); cp16(d + 48, s + 24);
    CP_COMMIT();
}

// ---------------- one K=64 chunk of MMA work (2-pass fp16 split) ----------------
template<bool RELU>
__device__ __forceinline__ void chunk_body(uint32_t ah_p, uint32_t al_p, uint32_t bb_p,
                                           int kr0, float acc[2][4][4]) {
#pragma unroll
    for (int ks = 0; ks < 4; ks++) {
        uint32_t akoff = (uint32_t)(kr0 + ks * 16) * 2;
        uint32_t a_h[2][4], a_l[2][4];
#pragma unroll
        for (int mt = 0; mt < 2; mt++) {
            uint32_t off = akoff + mt * (16 * AS * 2);
            ldmx4(a_h[mt], ah_p + off);
            ldmx4(a_l[mt], al_p + off);
            if (RELU) frag_relu(a_h[mt], a_l[mt]);
        }
        uint32_t b0[4], b1[4];
#pragma unroll
        for (int np = 0; np < 2; np++) {
            uint32_t boff = (uint32_t)(ks * 16) * 2 + np * (16 * BSB * 2);
            uint32_t r[4];
            ldmx4(r, bb_p + boff);
            b0[2*np] = r[0]; b0[2*np+1] = r[1]; b1[2*np] = r[2]; b1[2*np+1] = r[3];
        }
#pragma unroll
        for (int mt = 0; mt < 2; mt++)
#pragma unroll
            for (int nt = 0; nt < 4; nt++) mma16816(acc[mt][nt], a_h[mt], b0[nt], b1[nt]);
#pragma unroll
        for (int mt = 0; mt < 2; mt++)
#pragma unroll
            for (int nt = 0; nt < 4; nt++) mma16816(acc[mt][nt], a_l[mt], b0[nt], b1[nt]);
    }
}

__device__ __forceinline__ void zero_acc(float acc[2][4][4]) {
#pragma unroll
    for (int i = 0; i < 2; i++)
#pragma unroll
        for (int j = 0; j < 4; j++)
#pragma unroll
            for (int k = 0; k < 4; k++) acc[i][j][k] = 0.f;
}

// chunk schedule
__device__ __forceinline__ void bsched(int c, const __half* sc, const __half* w0,
                                       const __half* w1,
                                       const __half*& w, int& K, int& cc) {
    if (c < 4)       { w = sc; K = 256; cc = c; }
    else if (c < 8)  { w = w0; K = 256; cc = c - 4; }
    else if (c < 10) { w = w1; K = 128; cc = c - 8; }
    else             { w = g_w + WCOFF; K = 128; cc = c - 10; }
}

// ---------------- fused resnet block (PTILE=64, 2 CTAs/SM; blk==4 fuses proj) ----------------
__global__ void __launch_bounds__(256, 2)
resnet_kernel(int mode,
              const float* __restrict__ pts,
              const int* __restrict__ ixz, const int* __restrict__ ixy,
              const int* __restrict__ iyz,
              const float* __restrict__ fcpw, const float* __restrict__ fcpb,
              int blk,
              const float* __restrict__ fc0b, const float* __restrict__ fc1b,
              const float* __restrict__ bc) {
    extern __shared__ char smem[];
    uint32_t smb = smem_u32(smem);
    int tid = threadIdx.x;
    int lane = tid & 31, wid = tid >> 5;
    int m0 = (wid >> 2) * 32, n0 = (wid & 3) * 32;
    int pbase = blockIdx.x * PTILE;
    int* sbin = (int*)(smem + SM_SBIN);
    const int fuse = (blk == 4);
    const int NC = fuse ? 12 : 10;

    const __half* w0 = g_w + W0OFF + (size_t)blk * 32768;
    const __half* sc = g_w + SCOFF + (size_t)blk * 32768;
    const __half* w1 = g_w + W1OFF + (size_t)blk * 16384;

    // prime chunk 0 so DMA overlaps the A fill
    load_b(smb, sc, 256, 0, 0, tid);

    if (mode == 1 && tid < 192) {
        int pl = tid >> 6, s = tid & 63;
        int gp = pbase + s;
        int b = gp / TPTS;
        const int* ix = (pl == 0) ? ixz : (pl == 1) ? ixy : iyz;
        sbin[pl * PTILE + s] = (pl * BATCH + b) * R2 + ix[gp];
    }
    __syncthreads();

    // ---- fill A (x) hi/lo ----
    if (mode == 0) {
        int k = tid;
        u16* ah = (u16*)(smem + SM_AH) + k;
        u16* al = (u16*)(smem + SM_AL) + k;
        float wk0 = fcpw[k], wk1 = fcpw[256 + k], wk2 = fcpw[512 + k];
        float bk = fcpb[k];
        for (int s = 0; s < PTILE; s++) {
            int gp = pbase + s;
            float v = bk + pts[gp*3]*wk0 + pts[gp*3+1]*wk1 + pts[gp*3+2]*wk2;
            u16 h, l; dec2h(v, h, l);
            ah[s * AS] = h; al[s * AS] = l;
        }
    } else {
        // g_net half: units = 64 s x 32 ch4-groups, 8 per thread, MLP-batched float4
#pragma unroll
        for (int it = 0; it < 8; it++) {
            int uu = it * 256 + tid;
            int s = uu >> 5, c4 = (uu & 31) << 2;
            float4 v = *(const float4*)&g_net[(size_t)(pbase + s) * H + c4];
            dec4_store(smem, s * AS + c4, v);
        }
        // pooled half: 3 plane-row float4 loads per unit
#pragma unroll
        for (int it = 0; it < 8; it++) {
            int uu = it * 256 + tid;
            int s = uu >> 5, c4 = (uu & 31) << 2;
            float4 a = *(const float4*)&g_plane[(size_t)sbin[s] * H + c4];
            float4 b = *(const float4*)&g_plane[(size_t)sbin[PTILE + s] * H + c4];
            float4 c = *(const float4*)&g_plane[(size_t)sbin[2 * PTILE + s] * H + c4];
            float4 v = make_float4(a.x + b.x + c.x, a.y + b.y + c.y,
                                   a.z + b.z + c.z, a.w + b.w + c.w);
            dec4_store(smem, s * AS + 128 + c4, v);
        }
    }
    // (sync at iteration 0 orders fill vs ldmatrix)

    // per-thread ldmatrix base addresses
    uint32_t ah_p = smb + SM_AH + (uint32_t)((m0 + (lane & 15)) * AS + ((lane >> 4) << 3)) * 2;
    uint32_t al_p = smb + SM_AL + (uint32_t)((m0 + (lane & 15)) * AS + ((lane >> 4) << 3)) * 2;
    uint32_t b_rel = (uint32_t)((n0 + (lane & 15)) * BSB + ((lane >> 4) << 3)) * 2;

    float acc_sc[2][4][4], accB[2][4][4];
    zero_acc(acc_sc);
    zero_acc(accB);

    // ---- double-buffered chunk pipeline ----
    for (int c = 0; c < NC; c++) {
        if (c + 1 < NC) {
            const __half* nw; int nK, ncc;
            bsched(c + 1, sc, w0, w1, nw, nK, ncc);
            load_b(smb, nw, nK, ncc, (c + 1) & 1, tid);
            CP_WAIT1();
        } else CP_WAIT0();
        __syncthreads();

        if (c == 8) {
            // epilogue1: ns = relu(accB + b0) -> A region cols 0..127 (hi/lo)
#pragma unroll
            for (int mt = 0; mt < 2; mt++)
#pragma unroll
                for (int nt = 0; nt < 4; nt++) {
                    int row = m0 + mt * 16 + (lane >> 2);
                    int col = n0 + nt * 8 + (lane & 3) * 2;
                    float ba = fc0b[col], bb = fc0b[col + 1];
                    uint32_t lo, hi;
                    hi = dec2packh(fmaxf(accB[mt][nt][0] + ba, 0.f), fmaxf(accB[mt][nt][1] + bb, 0.f), lo);
                    *(uint32_t*)(smem + SM_AH + (row * AS + col) * 2) = hi;
                    *(uint32_t*)(smem + SM_AL + (row * AS + col) * 2) = lo;
                    hi = dec2packh(fmaxf(accB[mt][nt][2] + ba, 0.f), fmaxf(accB[mt][nt][3] + bb, 0.f), lo);
                    *(uint32_t*)(smem + SM_AH + ((row + 8) * AS + col) * 2) = hi;
                    *(uint32_t*)(smem + SM_AL + ((row + 8) * AS + col) * 2) = lo;
                }
            __syncthreads();
        }
        if (c == 10) {
            // epilogue2A (fused proj): out = acc_sc + b1 -> A region; reset accB
#pragma unroll
            for (int mt = 0; mt < 2; mt++)
#pragma unroll
                for (int nt = 0; nt < 4; nt++) {
                    int row = m0 + mt * 16 + (lane >> 2);
                    int col = n0 + nt * 8 + (lane & 3) * 2;
                    float ba = fc1b[col], bb = fc1b[col + 1];
                    uint32_t lo, hi;
                    hi = dec2packh(acc_sc[mt][nt][0] + ba, acc_sc[mt][nt][1] + bb, lo);
                    *(uint32_t*)(smem + SM_AH + (row * AS + col) * 2) = hi;
                    *(uint32_t*)(smem + SM_AL + (row * AS + col) * 2) = lo;
                    hi = dec2packh(acc_sc[mt][nt][2] + ba, acc_sc[mt][nt][3] + bb, lo);
                    *(uint32_t*)(smem + SM_AH + ((row + 8) * AS + col) * 2) = hi;
                    *(uint32_t*)(smem + SM_AL + ((row + 8) * AS + col) * 2) = lo;
                }
            zero_acc(accB);
            __syncthreads();
        }

        uint32_t bb_p = smb + SM_B + (uint32_t)(c & 1) * BBUF + b_rel;
        int kr0 = ((c < 4) ? c : (c < 8) ? (c - 4) : (c < 10) ? (c - 8) : (c - 10)) * 64;

        if (c < 4 || c == 8 || c == 9)
            chunk_body<false>(ah_p, al_p, bb_p, kr0, acc_sc);
        else if (c < 8)
            chunk_body<true>(ah_p, al_p, bb_p, kr0, accB);
        else
            chunk_body<false>(ah_p, al_p, bb_p, kr0, accB);

        __syncthreads();
    }

    // ---- final epilogue ----
    if (!fuse) {
#pragma unroll
        for (int mt = 0; mt < 2; mt++)
#pragma unroll
            for (int nt = 0; nt < 4; nt++) {
                int row = pbase + m0 + mt * 16 + (lane >> 2);
                int col = n0 + nt * 8 + (lane & 3) * 2;
                float ba = fc1b[col], bb = fc1b[col + 1];
                *(float2*)&g_net[(size_t)row * H + col] =
                    make_float2(acc_sc[mt][nt][0] + ba, acc_sc[mt][nt][1] + bb);
                *(float2*)&g_net[(size_t)(row + 8) * H + col] =
                    make_float2(acc_sc[mt][nt][2] + ba, acc_sc[mt][nt][3] + bb);
            }
    } else {
#pragma unroll
        for (int mt = 0; mt < 2; mt++)
#pragma unroll
            for (int nt = 0; nt < 4; nt++) {
                int row = pbase + m0 + mt * 16 + (lane >> 2);
                int col = n0 + nt * 8 + (lane & 3) * 2;
                float ba = bc[col], bb = bc[col + 1];
                *(float2*)&g_c[(size_t)row * H + col] =
                    make_float2(accB[mt][nt][0] + ba, accB[mt][nt][1] + bb);
                *(float2*)&g_c[(size_t)(row + 8) * H + col] =
                    make_float2(accB[mt][nt][2] + ba, accB[mt][nt][3] + bb);
            }
    }
}

// ---------------- weight prep: transpose + fp16 ----------------
__global__ void prep_w_kernel(const float* __restrict__ fc0w, const float* __restrict__ fc1w,
                              const float* __restrict__ scw,  const float* __restrict__ fccw) {
    int idx = blockIdx.x * 256 + threadIdx.x;
    if (idx >= WTOT) return;
    float v;
    if (idx < SCOFF) {
        int blk = idx >> 15, r = idx & 32767, out = r >> 8, k = r & 255;
        v = fc0w[((size_t)blk * 256 + k) * 128 + out];
    } else if (idx < W1OFF) {
        int i = idx - SCOFF;
        int blk = i >> 15, r = i & 32767, out = r >> 8, k = r & 255;
        v = scw[((size_t)blk * 256 + k) * 128 + out];
    } else if (idx < WCOFF) {
        int i = idx - W1OFF;
        int blk = i >> 14, r = i & 16383, out = r >> 7, k = r & 127;
        v = fc1w[((size_t)blk * 128 + k) * 128 + out];
    } else {
        int i = idx - WCOFF;
        int out = i >> 7, k = i & 127;
        v = fccw[(size_t)k * 128 + out];
    }
    g_w[idx] = __float2half_rn(v);
}

// ============ sorted-bin infrastructure ============
__global__ void zero_meta_kernel() {
    int i = blockIdx.x * 256 + threadIdx.x;
    if (i < CNTN) { g_cnt[i] = 0; g_cursor[i] = 0; }
}

__global__ void count_kernel(const int* __restrict__ ixz, const int* __restrict__ ixy,
                             const int* __restrict__ iyz) {
    int p = blockIdx.x * 256 + threadIdx.x;
    if (p >= NPTS) return;
    int b = p / TPTS;
    atomicAdd(&g_cnt[(0 * BATCH + b) * R2 + ixz[p]], 1);
    atomicAdd(&g_cnt[(1 * BATCH + b) * R2 + ixy[p]], 1);
    atomicAdd(&g_cnt[(2 * BATCH + b) * R2 + iyz[p]], 1);
}

__global__ void scan1_kernel() {
    __shared__ int smv[1024];
    int tid = threadIdx.x;
    int i = blockIdx.x * 1024 + tid;
    int v = g_cnt[i];
    smv[tid] = v;
    __syncthreads();
    for (int off = 1; off < 1024; off <<= 1) {
        int t = 0;
        if (tid >= off) t = smv[tid - off];
        __syncthreads();
        if (tid >= off) smv[tid] += t;
        __syncthreads();
    }
    g_start[i] = smv[tid] - v;
    if (tid == 1023) g_bsum[blockIdx.x] = smv[tid];
}

__global__ void scan2_kernel() {
    __shared__ int smv[128];
    int tid = threadIdx.x;
    int v = (tid < 96) ? g_bsum[tid] : 0;
    smv[tid] = v;
    __syncthreads();
    for (int off = 1; off < 128; off <<= 1) {
        int t = 0;
        if (tid >= off) t = smv[tid - off];
        __syncthreads();
        if (tid >= off) smv[tid] += t;
        __syncthreads();
    }
    if (tid < 96) g_bsum[tid] = smv[tid] - v;
}

__global__ void scan3_kernel() {
    int i = blockIdx.x * 256 + threadIdx.x;
    if (i < CNTN) g_start[i] += g_bsum[i >> 10];
}

__global__ void sortfill_kernel(const int* __restrict__ ixz, const int* __restrict__ ixy,
                                const int* __restrict__ iyz) {
    int p = blockIdx.x * 256 + threadIdx.x;
    if (p >= NPTS) return;
    int b = p / TPTS;
    int bins[3];
    bins[0] = (0 * BATCH + b) * R2 + ixz[p];
    bins[1] = (1 * BATCH + b) * R2 + ixy[p];
    bins[2] = (2 * BATCH + b) * R2 + iyz[p];
#pragma unroll
    for (int pl = 0; pl < 3; pl++) {
        int pos = atomicAdd(&g_cursor[bins[pl]], 1);
        g_sorted[g_start[bins[pl]] + pos] = p;
    }
}

__device__ __forceinline__ float4 max4(float4 a, float4 b) {
    return make_float4(fmaxf(a.x, b.x), fmaxf(a.y, b.y), fmaxf(a.z, b.z), fmaxf(a.w, b.w));
}

// pool max: warp-per-bin, MLP-8 batched float4 gathers. grid = CNTN/8, block 256.
__global__ void __launch_bounds__(256)
pool_max_kernel() {
    int w = threadIdx.x >> 5, lane = threadIdx.x & 31;
    int bin = blockIdx.x * 8 + w;
    int n = g_cnt[bin];
    if (n == 0) return;
    int st = g_start[bin];
    float4 v = make_float4(-FLT_MAX, -FLT_MAX, -FLT_MAX, -FLT_MAX);
    for (int i = 0; i < n; i += 8) {
        int m = n - i;
        int p0 = g_sorted[st + i];
        int p[8];
#pragma unroll
        for (int j = 0; j < 8; j++) p[j] = (j < m) ? g_sorted[st + i + j] : p0;
        float4 x[8];
#pragma unroll
        for (int j = 0; j < 8; j++) x[j] = *(const float4*)&g_net[(size_t)p[j] * H + lane * 4];
#pragma unroll
        for (int j = 0; j < 8; j++) if (j < m) v = max4(v, x[j]);
    }
    *(float4*)&g_plane[(size_t)bin * H + lane * 4] = v;
}

// plane mean: warp-per-bin MLP-8 float4 gather + smem transpose + coalesced writes.
__global__ void __launch_bounds__(128)
mean_kernel(float* __restrict__ out) {
    __shared__ float tile[128][33];
    int pb = blockIdx.x >> 7;
    int r0 = (blockIdx.x & 127) * 32;
    int tid = threadIdx.x;
    int w = tid >> 5, lane = tid & 31;

    for (int g = 0; g < 8; g++) {
        int bb = g * 4 + w;
        int bin = pb * R2 + r0 + bb;
        int n = g_cnt[bin];
        int st = g_start[bin];
        float4 s = make_float4(0.f, 0.f, 0.f, 0.f);
        for (int i = 0; i < n; i += 8) {
            int m = n - i;
            int p0 = g_sorted[st + i];
            int p[8];
#pragma unroll
            for (int j = 0; j < 8; j++) p[j] = (j < m) ? g_sorted[st + i + j] : p0;
            float4 x[8];
#pragma unroll
            for (int j = 0; j < 8; j++) x[j] = *(const float4*)&g_c[(size_t)p[j] * H + lane * 4];
#pragma unroll
            for (int j = 0; j < 8; j++)
                if (j < m) { s.x += x[j].x; s.y += x[j].y; s.z += x[j].z; s.w += x[j].w; }
        }
        float inv = 1.0f / (float)max(n, 1);
        tile[lane * 4 + 0][bb] = s.x * inv;
        tile[lane * 4 + 1][bb] = s.y * inv;
        tile[lane * 4 + 2][bb] = s.z * inv;
        tile[lane * 4 + 3][bb] = s.w * inv;
    }
    __syncthreads();
    int rowq = tid >> 5;
    for (int it = 0; it < 32; it++) {
        int row = it * 4 + rowq;
        out[((size_t)pb * H + row) * R2 + r0 + lane] = tile[row][lane];
    }
}

extern "C" void kernel_launch(void* const* d_in, const int* in_sizes, int n_in,
                              void* d_out, int out_size) {
    const float* pts  = (const float*)d_in[0];
    const int*   ixz  = (const int*)d_in[1];
    const int*   ixy  = (const int*)d_in[2];
    const int*   iyz  = (const int*)d_in[3];
    const float* fcpw = (const float*)d_in[4];
    const float* fcpb = (const float*)d_in[5];
    const float* fc0w = (const float*)d_in[6];
    const float* fc0b = (const float*)d_in[7];
    const float* fc1w = (const float*)d_in[8];
    const float* fc1b = (const float*)d_in[9];
    const float* scw  = (const float*)d_in[10];
    const float* fccw = (const float*)d_in[11];
    const float* fccb = (const float*)d_in[12];
    float* out = (float*)d_out;

    cudaFuncSetAttribute(resnet_kernel, cudaFuncAttributeMaxDynamicSharedMemorySize, SMEM_SZ);

    prep_w_kernel<<<(WTOT + 255) / 256, 256>>>(fc0w, fc1w, scw, fccw);   // 0
    zero_meta_kernel<<<(CNTN + 255) / 256, 256>>>();                     // 1
    count_kernel<<<(NPTS + 255) / 256, 256>>>(ixz, ixy, iyz);            // 2
    // resnet block 0 at index 3 (ncu -s 5 lands here)
    resnet_kernel<<<NTILES, 256, SMEM_SZ>>>(0, pts, ixz, ixy, iyz, fcpw, fcpb,
                                            0, fc0b, fc1b, fccb);        // 3
    scan1_kernel<<<96, 1024>>>();                                        // 4
    scan2_kernel<<<1, 128>>>();                                          // 5
    scan3_kernel<<<(CNTN + 255) / 256, 256>>>();                         // 6
    sortfill_kernel<<<(NPTS + 255) / 256, 256>>>(ixz, ixy, iyz);         // 7

    for (int it = 1; it < 5; it++) {
        pool_max_kernel<<<CNTN / 8, 256>>>();
        resnet_kernel<<<NTILES, 256, SMEM_SZ>>>(1, pts, ixz, ixy, iyz, fcpw, fcpb,
                                                it, fc0b + (size_t)it * H,
                                                fc1b + (size_t)it * H, fccb);
    }
    mean_kernel<<<24 * 128, 128>>>(out);
}